// round 11
// baseline (speedup 1.0000x reference)
#include <cuda_runtime.h>
#include <math.h>
#include <stdint.h>

#define NB 2
#define NA 16384
#define NM 32
#define NC 15
#define PI_F 3.14159265358979323846f
#define NBLK 148
#define NTHR 1024
#define GSZ (NBLK * NTHR)

typedef long long ll;

#define NEGK (-9223372036854775807ll - 1ll)
#define N4 NEGK, NEGK, NEGK, NEGK
#define N32 N4, N4, N4, N4, N4, N4, N4, N4

// ---------------- persistent scratch (zero-init; finalize restores all state) --------
__device__ float  g_md[NB][NA][NM];
__device__ ll     g_rowkey[NB][NA];                    // identity 0; reset in phase 3
__device__ ll     g_colkeyF[NB][NM];                   // identity 0; reset by finalize
__device__ ll     g_colkeyP[NB][NM] = {{N32}, {N32}};  // identity NEGK; reset by finalize
__device__ int    g_pairs[NB * NA * NM];
__device__ int    g_pairCount;                         // reset in phase 3
__device__ int    g_list[NB * NA];
__device__ int    g_listCount;                         // reset by finalize
__device__ double g_cls_sum[NB];                       // reset by finalize
__device__ double g_reg_sum[NB];
__device__ int    g_numpos[NB];
__device__ unsigned g_ticket;                          // reset by finalize
__device__ unsigned g_barCnt[3];                       // reset by finalize

__device__ __forceinline__ ll spack(float v, unsigned idx) {
    return (ll)((unsigned long long)__float_as_uint(v) << 32) - (ll)idx;
}
__device__ __forceinline__ void sdec(ll k, float& v, unsigned& idx) {
    unsigned lo = (unsigned)(k & 0xFFFFFFFFll);
    idx = (unsigned)(-(int)lo);
    unsigned vb = (unsigned)(((unsigned long long)(k + (ll)idx)) >> 32);
    v = __uint_as_float(vb);
}

__device__ __forceinline__ float warp_sum_f(float v) {
#pragma unroll
    for (int off = 16; off > 0; off >>= 1) v += __shfl_xor_sync(0xffffffffu, v, off);
    return v;
}

__device__ __forceinline__ float baseterm(float xr) {
    float x = fminf(fmaxf(xr, 0.0001f), 1.0f - 0.0001f);
    return 0.75f * x * x * (-__logf(1.0f - x + 1e-6f));
}

// grid barrier: pure busy-spin; reset by finalize.
__device__ __forceinline__ void grid_barrier(int k) {
    __syncthreads();
    if (threadIdx.x == 0) {
        __threadfence();
        atomicAdd(&g_barCnt[k], 1u);
        while (*(volatile unsigned*)&g_barCnt[k] < (unsigned)NBLK) {}
        __threadfence();
    }
    __syncthreads();
}

// Sutherland-Hodgman on centered f32 coordinates; float2 slots, exact cap 8.
__device__ float quad_inter_area_f(const float* ax, const float* ay,
                                   const float* bx, const float* by) {
    float2 p[8], q[8];
    int n = 4;
#pragma unroll
    for (int i = 0; i < 4; i++) p[i] = make_float2(ax[i], ay[i]);
    for (int e = 0; e < 4; e++) {
        float x0 = bx[e], y0 = by[e];
        int e2 = (e + 1) & 3;
        float dx = bx[e2] - x0, dy = by[e2] - y0;
        int m = 0;
        float2 prev = p[n - 1];
        float dprev = dx * (prev.y - y0) - dy * (prev.x - x0);
        for (int i = 0; i < n; i++) {
            float2 cur = p[i];
            float dc = dx * (cur.y - y0) - dy * (cur.x - x0);
            bool inc = (dc >= 0.0f), inp = (dprev >= 0.0f);
            if (inc != inp) {
                float t = dprev / (dprev - dc);
                q[m] = make_float2(prev.x + t * (cur.x - prev.x),
                                   prev.y + t * (cur.y - prev.y));
                m++;
            }
            if (inc) { q[m] = cur; m++; }
            dprev = dc; prev = cur;
        }
        n = m;
        if (n == 0) return 0.0f;
        for (int i = 0; i < n; i++) p[i] = q[i];
    }
    if (n < 3) return 0.0f;
    float s = 0.0f;
    float2 pp = p[n - 1];
    for (int i = 0; i < n; i++) {
        s += pp.x * p[i].y - p[i].x * pp.y;
        pp = p[i];
    }
    return 0.5f * fabsf(s);
}

// gate test: FMA compare with exact-division fallback in the ambiguous band
__device__ __forceinline__ bool gate(float inter, float denom) {
    float lhs = inter * 10.0f;
    bool f = (lhs >= denom);
    if (fabsf(lhs - denom) < 1e-4f * denom) f = (inter / denom >= 0.1f);
    return f;
}

// ================ the single persistent kernel ================
__global__ void __launch_bounds__(NTHR, 1) k_all(const float* __restrict__ cls,
                                                 const float* __restrict__ reg,
                                                 const float* __restrict__ anc,
                                                 const float* __restrict__ ranc,
                                                 const float* __restrict__ ann,
                                                 float* __restrict__ out) {
    int tid = threadIdx.x;
    int lane = tid & 31;
    int gtid = blockIdx.x * NTHR + tid;

    __shared__ float sgx[NB * NM][4], sgy[NB * NM][4], sgar[NB * NM];
    __shared__ float sqx1[NB * NM], sqy1[NB * NM], sqx2[NB * NM], sqy2[NB * NM], sqar[NB * NM];
    __shared__ ll scol[NB * NM];

    if (tid < NB * NM) {
        int img = tid >> 5, j = tid & 31;
        const float* g = ann + (size_t)(img * NM + j) * 6;
        float cx = g[0], cy = g[1], w = g[2], h = g[3];
        float th = g[4] * (PI_F / 180.0f);
        float sn, cs;
        sincosf(th, &sn, &cs);   // precise: only 64 calls
        const float lx[4] = {-0.5f, 0.5f, 0.5f, -0.5f};
        const float ly[4] = {-0.5f, -0.5f, 0.5f, 0.5f};
#pragma unroll
        for (int k = 0; k < 4; k++) {
            float dx = w * lx[k], dy = h * ly[k];
            sgx[tid][k] = cx + dx * cs - dy * sn;
            sgy[tid][k] = cy + dx * sn + dy * cs;
        }
        sgar[tid] = w * h;
        float s = fmaxf(w, h) * 0.5f;
        sqx1[tid] = cx - s; sqy1[tid] = cy - s;
        sqx2[tid] = cx + s; sqy2[tid] = cy + s;
        sqar[tid] = (2.0f * s) * (2.0f * s);
        scol[tid] = 0;
    }
    __syncthreads();

    // -------- Phase 1: filter, QUARTER-row per thread (8 gts) --------
    if (gtid < NB * NA * 4) {
        int quarter = gtid & 3;
        int a = (gtid >> 2) & (NA - 1);
        int img = gtid >> 16;
        int aidx = img * NA + a;
        const float* p = anc + (size_t)aidx * 5;
        const float* q = ranc + (size_t)aidx * 5;
        float s0 = fmaxf(p[2], p[3]) * 0.5f;
        float ax1 = p[0] - s0, ay1 = p[1] - s0, ax2 = p[0] + s0, ay2 = p[1] + s0;
        float aar = (ax2 - ax1) * (ay2 - ay1);
        float s1 = fmaxf(q[2], q[3]) * 0.5f;
        float rx1 = q[0] - s1, ry1 = q[1] - s1, rx2 = q[0] + s1, ry2 = q[1] + s1;
        float rar = (rx2 - rx1) * (ry2 - ry1);
        int jb = (img << 5) + quarter * 8;

        int m = 0;
        unsigned fbits0 = 0, fbits1 = 0;
#pragma unroll
        for (int jj = 0; jj < 8; jj++) {
            float gx1 = sqx1[jb + jj], gy1 = sqy1[jb + jj];
            float gx2 = sqx2[jb + jj], gy2 = sqy2[jb + jj], gar = sqar[jb + jj];
            float wx = fmaxf(fminf(ax2, gx2) - fmaxf(ax1, gx1), 0.0f);
            float wy = fmaxf(fminf(ay2, gy2) - fmaxf(ay1, gy1), 0.0f);
            float i0 = wx * wy;
            bool f0 = gate(i0, aar + gar - i0 + 1e-8f);
            wx = fmaxf(fminf(rx2, gx2) - fmaxf(rx1, gx1), 0.0f);
            wy = fmaxf(fminf(ry2, gy2) - fmaxf(ry1, gy1), 0.0f);
            float i1 = wx * wy;
            bool f1 = gate(i1, rar + gar - i1 + 1e-8f);
            fbits0 |= ((unsigned)f0) << jj;
            fbits1 |= ((unsigned)f1) << jj;
            m += (int)(f0 | f1);
        }
        int incl = m;
#pragma unroll
        for (int off = 1; off < 32; off <<= 1) {
            int nn = __shfl_up_sync(0xffffffffu, incl, off);
            if (lane >= off) incl += nn;
        }
        int total = __shfl_sync(0xffffffffu, incl, 31);
        int base = 0;
        if (lane == 0 && total > 0) base = atomicAdd(&g_pairCount, total);
        base = __shfl_sync(0xffffffffu, base, 0);
        int off0 = base + incl - m;
        unsigned both = fbits0 | fbits1;
        while (both) {
            int jj = __ffs(both) - 1;
            both &= both - 1;
            int j = quarter * 8 + jj;
            int f0 = (fbits0 >> jj) & 1, f1 = (fbits1 >> jj) & 1;
            g_pairs[off0++] = (img << 21) | (a << 7) | (j << 2) | (f1 << 1) | f0;
        }
    }

    grid_barrier(0);

    // ---------------- Phase 2: heavy (grid-stride clip) ----------------
    {
        int total = g_pairCount;
        const float lx[4] = {-0.5f, 0.5f, 0.5f, -0.5f};
        const float ly[4] = {-0.5f, -0.5f, 0.5f, 0.5f};
        for (int idx = gtid; idx < total; idx += GSZ) {
            int code = g_pairs[idx];
            int f0 = code & 1, f1 = (code >> 1) & 1;
            int j = (code >> 2) & 31;
            int a = (code >> 7) & (NA - 1);
            int img = (code >> 21) & 1;
            int gj = (img << 5) + j;
            float gar = sgar[gj];
            float bf = 0.0f, af = 0.0f;
#pragma unroll
            for (int ph = 0; ph < 2; ph++) {
                if (!(ph ? f1 : f0)) continue;
                const float* pp = (ph ? ranc : anc) + (size_t)(img * NA + a) * 5;
                float cx = pp[0], cy = pp[1], w = pp[2], h = pp[3];
                float th = pp[4] * (PI_F / 180.0f);
                float sn, cs;
                __sincosf(th, &sn, &cs);
                float AX[4], AY[4], BX[4], BY[4];
#pragma unroll
                for (int k = 0; k < 4; k++) {
                    float dx = w * lx[k], dy = h * ly[k];
                    AX[k] = dx * cs - dy * sn;
                    AY[k] = dx * sn + dy * cs;
                    BX[k] = sgx[gj][k] - cx;
                    BY[k] = sgy[gj][k] - cy;
                }
                float inter = quad_inter_area_f(AX, AY, BX, BY);
                float iou = inter / (w * h + gar - inter + 1e-8f);
                if (ph) af = iou; else bf = iou;
            }
            float md = fabsf(bf + 0.5f * af - fabsf(af - bf));
            g_md[img][a][j] = md;
            atomicMax(&g_rowkey[img][a], spack(md, (unsigned)j));
            if (md > 0.0f) atomicMax(&scol[gj], spack(md, (unsigned)a));
        }
        __syncthreads();
        if (tid < NB * NM && scol[tid] > 0)
            atomicMax(&g_colkeyF[tid >> 5][tid & 31], scol[tid]);
    }

    grid_barrier(1);

    // ---------------- Phase 3: colmax + force + compaction ----------------
    __shared__ int sforce[NB * NM];
    __shared__ ll scolp[NB * NM];
    __shared__ int snp[NB];
    if (tid < NB * NM) {
        float v; unsigned ix;
        sdec(g_colkeyF[tid >> 5][tid & 31], v, ix);
        sforce[tid] = (v < 0.5f) ? (int)ix : -1;
        scolp[tid] = NEGK;
    }
    if (tid == 128) { snp[0] = 0; snp[1] = 0; }
    if (gtid == GSZ - 1) g_pairCount = 0;  // consumed; reset for next replay
    __syncthreads();

    if (gtid < NB * NA) {
        int a = gtid & (NA - 1);
        int img = gtid >> 14;
        int jb = img << 5;
        ll rk = g_rowkey[img][a];
        if (rk != 0) g_rowkey[img][a] = 0;  // restore identity
        float iomax; unsigned jm;
        sdec(rk, iomax, jm);
        bool pos = (iomax >= 0.5f);
#pragma unroll
        for (int j = 0; j < NM; j++) pos |= (sforce[jb + j] == a);
        if (pos) {
            const float4* mrow = (const float4*)g_md[img][a];
#pragma unroll
            for (int c = 0; c < 8; c++) {
                float4 m = mrow[c];
                atomicMax(&scolp[jb + c * 4 + 0], spack(m.x, (unsigned)a));
                atomicMax(&scolp[jb + c * 4 + 1], spack(m.y, (unsigned)a));
                atomicMax(&scolp[jb + c * 4 + 2], spack(m.z, (unsigned)a));
                atomicMax(&scolp[jb + c * 4 + 3], spack(m.w, (unsigned)a));
            }
        }
        bool emit = pos || (iomax >= 0.4f);
        unsigned mask = __ballot_sync(0xffffffffu, emit);
        if (mask) {
            int leader = __ffs(mask) - 1;
            int rank = __popc(mask & ((1u << lane) - 1));
            int base = 0;
            if (lane == leader) base = atomicAdd(&g_listCount, __popc(mask));
            base = __shfl_sync(0xffffffffu, base, leader);
            if (emit)
                g_list[base + rank] = a | (img << 14) | ((int)pos << 15) | ((int)jm << 16);
        }
        unsigned pmask = __ballot_sync(0xffffffffu, pos);
        if (lane == 0 && pmask) atomicAdd(&snp[img], __popc(pmask));
    }
    __syncthreads();
    if (tid < NB * NM && scolp[tid] != NEGK)
        atomicMax(&g_colkeyP[tid >> 5][tid & 31], scolp[tid]);
    if (tid == 128 && snp[0]) atomicAdd(&g_numpos[0], snp[0]);
    if (tid == 129 && snp[1]) atomicAdd(&g_numpos[1], snp[1]);

    grid_barrier(2);

    // ---- stage final colkeyP into shared (decoded) for fast corrections ----
    __shared__ float smaxP[NB * NM];
    __shared__ int sargP[NB * NM];
    if (tid < NB * NM) {
        float v; unsigned ix;
        sdec(g_colkeyP[tid >> 5][tid & 31], v, ix);
        smaxP[tid] = v; sargP[tid] = (int)ix;
    }
    __syncthreads();

    // ---------------- Phase 4: dense base sum + sparse corrections ----------------
    float cs0 = 0.0f, cs1 = 0.0f, rs0 = 0.0f, rs1 = 0.0f;
    {
        const float4* c4 = (const float4*)cls;
        const int HALF = NA * NC / 4;  // 61440 float4 per image
        for (int i = gtid; i < 2 * HALF; i += GSZ) {
            float4 v = c4[i];
            float s = baseterm(v.x) + baseterm(v.y) + baseterm(v.z) + baseterm(v.w);
            if (i < HALF) cs0 += s; else cs1 += s;
        }
    }
    {
        int nitems = g_listCount;
        for (int i = gtid; i < nitems; i += GSZ) {
            int code = g_list[i];
            int a = code & (NA - 1);
            int img = (code >> 14) & 1;
            int pos = (code >> 15) & 1;
            int jm = (code >> 16) & 31;
            int jb = img << 5;
            const float* crow = cls + ((size_t)img * NA + a) * NC;
            float cc = 0.0f, rr = 0.0f;
            if (!pos) {
                float s = 0.0f;
#pragma unroll
                for (int c = 0; c < NC; c++) s += baseterm(crow[c]);
                cc = -s;
            } else {
                float mw = -1e30f;
                const float4* mrow = (const float4*)g_md[img][a];
#pragma unroll
                for (int c = 0; c < 8; c++) {
                    float4 m = mrow[c];
                    float mv[4] = {m.x, m.y, m.z, m.w};
#pragma unroll
                    for (int k = 0; k < 4; k++) {
                        int j = c * 4 + k;
                        float md = mv[k];
                        bool pm = (md >= 0.5f) || (sargP[jb + j] == a);
                        float comp = pm ? (1.0f - smaxP[jb + j]) : md;
                        mw = fmaxf(mw, comp + md);
                    }
                }
                const float* gt = ann + (size_t)(img * NM + jm) * 6;
                int lab = (int)gt[5];
                float xl = fminf(fmaxf(crow[lab], 0.0001f), 1.0f - 0.0001f);
                float posterm = 0.25f * (1.0f - xl) * (1.0f - xl) * (-__logf(xl + 1e-6f)) * (mw + 1.0f);
                cc = posterm - baseterm(crow[lab]);
                const float* ap = anc + (size_t)(img * NA + a) * 5;
                const float* rg = reg + (size_t)(img * NA + a) * 5;
                float tv[5];
                tv[0] = (gt[0] - ap[0]) / ap[2];
                tv[1] = (gt[1] - ap[1]) / ap[3];
                tv[2] = __logf(fmaxf(gt[2], 1.0f) / ap[2]);
                tv[3] = __logf(fmaxf(gt[3], 1.0f) / ap[3]);
                tv[4] = __tanf(gt[4] * (PI_F / 180.0f)) - __tanf(ap[4] * (PI_F / 180.0f));
                const float BETA = (float)(1.0 / 9.0);
#pragma unroll
                for (int k = 0; k < 5; k++) {
                    float diff = fabsf(rg[k] - tv[k]);
                    float sl = (diff < BETA) ? (0.5f * diff * diff / BETA) : (diff - 0.5f * BETA);
                    rr += sl * mw;
                }
            }
            if (img == 0) { cs0 += cc; rs0 += rr; } else { cs1 += cc; rs1 += rr; }
        }
    }

    // ---------------- block reduction + ticket finalize ----------------
    cs0 = warp_sum_f(cs0); cs1 = warp_sum_f(cs1);
    rs0 = warp_sum_f(rs0); rs1 = warp_sum_f(rs1);
    __shared__ float sc0[32], sc1[32], sr0[32], sr1[32];
    int warp = tid >> 5;
    if (lane == 0) { sc0[warp] = cs0; sc1[warp] = cs1; sr0[warp] = rs0; sr1[warp] = rs1; }
    __syncthreads();
    __shared__ bool lastf;
    if (tid == 0) {
        double c0 = 0.0, c1 = 0.0, r0 = 0.0, r1 = 0.0;
#pragma unroll
        for (int k = 0; k < 32; k++) {
            c0 += (double)sc0[k]; c1 += (double)sc1[k];
            r0 += (double)sr0[k]; r1 += (double)sr1[k];
        }
        if (c0 != 0.0) atomicAdd(&g_cls_sum[0], c0);
        if (c1 != 0.0) atomicAdd(&g_cls_sum[1], c1);
        if (r0 != 0.0) atomicAdd(&g_reg_sum[0], r0);
        if (r1 != 0.0) atomicAdd(&g_reg_sum[1], r1);
        __threadfence();
        unsigned tk = atomicAdd(&g_ticket, 1u);
        lastf = (tk == (unsigned)(NBLK - 1));
    }
    __syncthreads();
    if (lastf) {
        if (tid < NB * NM) {
            g_colkeyF[tid >> 5][tid & 31] = 0;
            g_colkeyP[tid >> 5][tid & 31] = NEGK;
        }
        if (tid == 64) g_listCount = 0;
        if (tid == 65) g_ticket = 0;
        if (tid == 66) { g_barCnt[0] = 0; g_barCnt[1] = 0; g_barCnt[2] = 0; }
        if (tid == 0) {
            double lc = 0.0, lr = 0.0;
#pragma unroll
            for (int i2 = 0; i2 < NB; i2++) {
                int np = g_numpos[i2];
                lc += g_cls_sum[i2] / fmax((double)np, 1.0);
                if (np > 0) lr += g_reg_sum[i2] / (double)(np * 5);
                g_cls_sum[i2] = 0.0; g_reg_sum[i2] = 0.0; g_numpos[i2] = 0;
            }
            out[0] = (float)(lc / (double)NB);
            out[1] = (float)(lr / (double)NB);
        }
    }
}

// ---------------- launcher: ONE kernel ----------------
extern "C" void kernel_launch(void* const* d_in, const int* in_sizes, int n_in,
                              void* d_out, int out_size) {
    const float* cls  = (const float*)d_in[0];
    const float* reg  = (const float*)d_in[1];
    const float* anc  = (const float*)d_in[2];
    const float* ranc = (const float*)d_in[3];
    const float* ann  = (const float*)d_in[4];
    float* out = (float*)d_out;

    k_all<<<NBLK, NTHR>>>(cls, reg, anc, ranc, ann, out);
}

// round 12
// speedup vs baseline: 1.3182x; 1.3182x over previous
#include <cuda_runtime.h>
#include <math.h>
#include <stdint.h>

#define NB 2
#define NA 16384
#define NM 32
#define NC 15
#define PI_F 3.14159265358979323846f
#define NBLK 148
#define NTHR 512
#define GSZ (NBLK * NTHR)

typedef long long ll;

#define NEGK (-9223372036854775807ll - 1ll)
#define N4 NEGK, NEGK, NEGK, NEGK
#define N32 N4, N4, N4, N4, N4, N4, N4, N4

// ---------------- persistent scratch (zero-init; finalize restores all state) --------
__device__ float  g_md[NB][NA][NM];
__device__ ll     g_rowkey[NB][NA];                    // identity 0; reset in phase 3
__device__ ll     g_colkeyF[NB][NM];                   // identity 0; reset by finalize
__device__ ll     g_colkeyP[NB][NM] = {{N32}, {N32}};  // identity NEGK; reset by finalize
__device__ int    g_pairs[NB * NA * NM];
__device__ int    g_pairCount;                         // reset in phase 3
__device__ int    g_list[NB * NA];
__device__ int    g_listCount;                         // reset by finalize
__device__ double g_cls_sum[NB];                       // reset by finalize
__device__ double g_reg_sum[NB];
__device__ int    g_numpos[NB];
__device__ unsigned g_ticket;                          // reset by finalize
__device__ unsigned g_barCnt[3];                       // reset by finalize

__device__ __forceinline__ ll spack(float v, unsigned idx) {
    return (ll)((unsigned long long)__float_as_uint(v) << 32) - (ll)idx;
}
__device__ __forceinline__ void sdec(ll k, float& v, unsigned& idx) {
    unsigned lo = (unsigned)(k & 0xFFFFFFFFll);
    idx = (unsigned)(-(int)lo);
    unsigned vb = (unsigned)(((unsigned long long)(k + (ll)idx)) >> 32);
    v = __uint_as_float(vb);
}

__device__ __forceinline__ float warp_sum_f(float v) {
#pragma unroll
    for (int off = 16; off > 0; off >>= 1) v += __shfl_xor_sync(0xffffffffu, v, off);
    return v;
}

__device__ __forceinline__ float baseterm(float xr) {
    float x = fminf(fmaxf(xr, 0.0001f), 1.0f - 0.0001f);
    return 0.75f * x * x * (-__logf(1.0f - x + 1e-6f));
}

// grid barrier: pure busy-spin; reset by finalize.
__device__ __forceinline__ void grid_barrier(int k) {
    __syncthreads();
    if (threadIdx.x == 0) {
        __threadfence();
        atomicAdd(&g_barCnt[k], 1u);
        while (*(volatile unsigned*)&g_barCnt[k] < (unsigned)NBLK) {}
        __threadfence();
    }
    __syncthreads();
}

// Sutherland-Hodgman on centered f32 coordinates; float2 slots, exact cap 8.
__device__ float quad_inter_area_f(const float* ax, const float* ay,
                                   const float* bx, const float* by) {
    float2 p[8], q[8];
    int n = 4;
#pragma unroll
    for (int i = 0; i < 4; i++) p[i] = make_float2(ax[i], ay[i]);
    for (int e = 0; e < 4; e++) {
        float x0 = bx[e], y0 = by[e];
        int e2 = (e + 1) & 3;
        float dx = bx[e2] - x0, dy = by[e2] - y0;
        int m = 0;
        float2 prev = p[n - 1];
        float dprev = dx * (prev.y - y0) - dy * (prev.x - x0);
        for (int i = 0; i < n; i++) {
            float2 cur = p[i];
            float dc = dx * (cur.y - y0) - dy * (cur.x - x0);
            bool inc = (dc >= 0.0f), inp = (dprev >= 0.0f);
            if (inc != inp) {
                float t = dprev / (dprev - dc);
                q[m] = make_float2(prev.x + t * (cur.x - prev.x),
                                   prev.y + t * (cur.y - prev.y));
                m++;
            }
            if (inc) { q[m] = cur; m++; }
            dprev = dc; prev = cur;
        }
        n = m;
        if (n == 0) return 0.0f;
        for (int i = 0; i < n; i++) p[i] = q[i];
    }
    if (n < 3) return 0.0f;
    float s = 0.0f;
    float2 pp = p[n - 1];
    for (int i = 0; i < n; i++) {
        s += pp.x * p[i].y - p[i].x * pp.y;
        pp = p[i];
    }
    return 0.5f * fabsf(s);
}

// gate test: FMA compare with exact-division fallback in the ambiguous band
__device__ __forceinline__ bool gate(float inter, float denom) {
    float lhs = inter * 10.0f;
    bool f = (lhs >= denom);
    if (fabsf(lhs - denom) < 1e-4f * denom) f = (inter / denom >= 0.1f);
    return f;
}

// ================ the single persistent kernel ================
__global__ void __launch_bounds__(NTHR, 1) k_all(const float* __restrict__ cls,
                                                 const float* __restrict__ reg,
                                                 const float* __restrict__ anc,
                                                 const float* __restrict__ ranc,
                                                 const float* __restrict__ ann,
                                                 float* __restrict__ out) {
    int tid = threadIdx.x;
    int lane = tid & 31;
    int gtid = blockIdx.x * NTHR + tid;

    // loss accumulators live across all phases
    float cs0 = 0.0f, cs1 = 0.0f, rs0 = 0.0f, rs1 = 0.0f;
    const float4* c4 = (const float4*)cls;
    const int HALF = NA * NC / 4;  // 61440 float4 per image; 2*HALF total

    __shared__ float sgx[NB * NM][4], sgy[NB * NM][4], sgar[NB * NM];
    __shared__ float sqx1[NB * NM], sqy1[NB * NM], sqx2[NB * NM], sqy2[NB * NM], sqar[NB * NM];
    __shared__ ll scol[NB * NM];

    if (tid < NB * NM) {
        int img = tid >> 5, j = tid & 31;
        const float* g = ann + (size_t)(img * NM + j) * 6;
        float cx = g[0], cy = g[1], w = g[2], h = g[3];
        float th = g[4] * (PI_F / 180.0f);
        float sn, cs;
        sincosf(th, &sn, &cs);   // precise: only 64 calls
        const float lx[4] = {-0.5f, 0.5f, 0.5f, -0.5f};
        const float ly[4] = {-0.5f, -0.5f, 0.5f, 0.5f};
#pragma unroll
        for (int k = 0; k < 4; k++) {
            float dx = w * lx[k], dy = h * ly[k];
            sgx[tid][k] = cx + dx * cs - dy * sn;
            sgy[tid][k] = cy + dx * sn + dy * cs;
        }
        sgar[tid] = w * h;
        float s = fmaxf(w, h) * 0.5f;
        sqx1[tid] = cx - s; sqy1[tid] = cy - s;
        sqx2[tid] = cx + s; sqy2[tid] = cy + s;
        sqar[tid] = (2.0f * s) * (2.0f * s);
        scol[tid] = 0;
    }
    __syncthreads();

    // -------- Phase 1: filter (half-row per thread) + dense base-sum iteration 0 ------
    if (gtid < NB * NA * 2) {
        int half = gtid & 1;
        int a = (gtid >> 1) & (NA - 1);
        int img = gtid >> 15;
        int aidx = img * NA + a;
        const float* p = anc + (size_t)aidx * 5;
        const float* q = ranc + (size_t)aidx * 5;
        float s0 = fmaxf(p[2], p[3]) * 0.5f;
        float ax1 = p[0] - s0, ay1 = p[1] - s0, ax2 = p[0] + s0, ay2 = p[1] + s0;
        float aar = (ax2 - ax1) * (ay2 - ay1);
        float s1 = fmaxf(q[2], q[3]) * 0.5f;
        float rx1 = q[0] - s1, ry1 = q[1] - s1, rx2 = q[0] + s1, ry2 = q[1] + s1;
        float rar = (rx2 - rx1) * (ry2 - ry1);
        int jb = (img << 5) + half * 16;

        int m = 0;
        unsigned fbits0 = 0, fbits1 = 0;
#pragma unroll
        for (int jj = 0; jj < 16; jj++) {
            float gx1 = sqx1[jb + jj], gy1 = sqy1[jb + jj];
            float gx2 = sqx2[jb + jj], gy2 = sqy2[jb + jj], gar = sqar[jb + jj];
            float wx = fmaxf(fminf(ax2, gx2) - fmaxf(ax1, gx1), 0.0f);
            float wy = fmaxf(fminf(ay2, gy2) - fmaxf(ay1, gy1), 0.0f);
            float i0 = wx * wy;
            bool f0 = gate(i0, aar + gar - i0 + 1e-8f);
            wx = fmaxf(fminf(rx2, gx2) - fmaxf(rx1, gx1), 0.0f);
            wy = fmaxf(fminf(ry2, gy2) - fmaxf(ry1, gy1), 0.0f);
            float i1 = wx * wy;
            bool f1 = gate(i1, rar + gar - i1 + 1e-8f);
            fbits0 |= ((unsigned)f0) << jj;
            fbits1 |= ((unsigned)f1) << jj;
            m += (int)(f0 | f1);
        }
        int incl = m;
#pragma unroll
        for (int off = 1; off < 32; off <<= 1) {
            int nn = __shfl_up_sync(0xffffffffu, incl, off);
            if (lane >= off) incl += nn;
        }
        int total = __shfl_sync(0xffffffffu, incl, 31);
        int base = 0;
        if (lane == 0 && total > 0) base = atomicAdd(&g_pairCount, total);
        base = __shfl_sync(0xffffffffu, base, 0);
        int off0 = base + incl - m;
        unsigned both = fbits0 | fbits1;
        while (both) {
            int jj = __ffs(both) - 1;
            both &= both - 1;
            int j = half * 16 + jj;
            int f0 = (fbits0 >> jj) & 1, f1 = (fbits1 >> jj) & 1;
            g_pairs[off0++] = (img << 21) | (a << 7) | (j << 2) | (f1 << 1) | f0;
        }
    }
    // dense base-sum, iteration 0 (independent work; overlaps filter stalls)
    {
        int i = gtid;
        if (i < 2 * HALF) {
            float4 v = c4[i];
            float s = baseterm(v.x) + baseterm(v.y) + baseterm(v.z) + baseterm(v.w);
            if (i < HALF) cs0 += s; else cs1 += s;
        }
    }

    grid_barrier(0);

    // ---------------- Phase 2: heavy clip + dense base-sum iteration 1 ----------------
    {
        int total = g_pairCount;
        const float lx[4] = {-0.5f, 0.5f, 0.5f, -0.5f};
        const float ly[4] = {-0.5f, -0.5f, 0.5f, 0.5f};
        for (int idx = gtid; idx < total; idx += GSZ) {
            int code = g_pairs[idx];
            int f0 = code & 1, f1 = (code >> 1) & 1;
            int j = (code >> 2) & 31;
            int a = (code >> 7) & (NA - 1);
            int img = (code >> 21) & 1;
            int gj = (img << 5) + j;
            float gar = sgar[gj];
            float bf = 0.0f, af = 0.0f;
#pragma unroll
            for (int ph = 0; ph < 2; ph++) {
                if (!(ph ? f1 : f0)) continue;
                const float* pp = (ph ? ranc : anc) + (size_t)(img * NA + a) * 5;
                float cx = pp[0], cy = pp[1], w = pp[2], h = pp[3];
                float th = pp[4] * (PI_F / 180.0f);
                float sn, cs;
                __sincosf(th, &sn, &cs);
                float AX[4], AY[4], BX[4], BY[4];
#pragma unroll
                for (int k = 0; k < 4; k++) {
                    float dx = w * lx[k], dy = h * ly[k];
                    AX[k] = dx * cs - dy * sn;
                    AY[k] = dx * sn + dy * cs;
                    BX[k] = sgx[gj][k] - cx;
                    BY[k] = sgy[gj][k] - cy;
                }
                float inter = quad_inter_area_f(AX, AY, BX, BY);
                float iou = inter / (w * h + gar - inter + 1e-8f);
                if (ph) af = iou; else bf = iou;
            }
            float md = fabsf(bf + 0.5f * af - fabsf(af - bf));
            g_md[img][a][j] = md;
            atomicMax(&g_rowkey[img][a], spack(md, (unsigned)j));
            if (md > 0.0f) atomicMax(&scol[gj], spack(md, (unsigned)a));
        }
        // dense base-sum, iteration 1 (overlaps heavy-clip stalls)
        {
            int i = gtid + GSZ;
            if (i < 2 * HALF) {
                float4 v = c4[i];
                float s = baseterm(v.x) + baseterm(v.y) + baseterm(v.z) + baseterm(v.w);
                if (i < HALF) cs0 += s; else cs1 += s;
            }
        }
        __syncthreads();
        if (tid < NB * NM && scol[tid] > 0)
            atomicMax(&g_colkeyF[tid >> 5][tid & 31], scol[tid]);
    }

    grid_barrier(1);

    // ---------------- Phase 3: colmax + force + compaction ----------------
    __shared__ int sforce[NB * NM];
    __shared__ ll scolp[NB * NM];
    __shared__ int snp[NB];
    if (tid < NB * NM) {
        float v; unsigned ix;
        sdec(g_colkeyF[tid >> 5][tid & 31], v, ix);
        sforce[tid] = (v < 0.5f) ? (int)ix : -1;
        scolp[tid] = NEGK;
    }
    if (tid == 128) { snp[0] = 0; snp[1] = 0; }
    if (gtid == GSZ - 1) g_pairCount = 0;  // consumed; reset for next replay
    __syncthreads();

    if (gtid < NB * NA) {
        int a = gtid & (NA - 1);
        int img = gtid >> 14;
        int jb = img << 5;
        ll rk = g_rowkey[img][a];
        if (rk != 0) g_rowkey[img][a] = 0;  // restore identity
        float iomax; unsigned jm;
        sdec(rk, iomax, jm);
        bool pos = (iomax >= 0.5f);
#pragma unroll
        for (int j = 0; j < NM; j++) pos |= (sforce[jb + j] == a);
        if (pos) {
            const float4* mrow = (const float4*)g_md[img][a];
#pragma unroll
            for (int c = 0; c < 8; c++) {
                float4 m = mrow[c];
                atomicMax(&scolp[jb + c * 4 + 0], spack(m.x, (unsigned)a));
                atomicMax(&scolp[jb + c * 4 + 1], spack(m.y, (unsigned)a));
                atomicMax(&scolp[jb + c * 4 + 2], spack(m.z, (unsigned)a));
                atomicMax(&scolp[jb + c * 4 + 3], spack(m.w, (unsigned)a));
            }
        }
        bool emit = pos || (iomax >= 0.4f);
        unsigned mask = __ballot_sync(0xffffffffu, emit);
        if (mask) {
            int leader = __ffs(mask) - 1;
            int rank = __popc(mask & ((1u << lane) - 1));
            int base = 0;
            if (lane == leader) base = atomicAdd(&g_listCount, __popc(mask));
            base = __shfl_sync(0xffffffffu, base, leader);
            if (emit)
                g_list[base + rank] = a | (img << 14) | ((int)pos << 15) | ((int)jm << 16);
        }
        unsigned pmask = __ballot_sync(0xffffffffu, pos);
        if (lane == 0 && pmask) atomicAdd(&snp[img], __popc(pmask));
    }
    __syncthreads();
    if (tid < NB * NM && scolp[tid] != NEGK)
        atomicMax(&g_colkeyP[tid >> 5][tid & 31], scolp[tid]);
    if (tid == 128 && snp[0]) atomicAdd(&g_numpos[0], snp[0]);
    if (tid == 129 && snp[1]) atomicAdd(&g_numpos[1], snp[1]);

    grid_barrier(2);

    // ---- stage final colkeyP into shared (decoded) for fast corrections ----
    __shared__ float smaxP[NB * NM];
    __shared__ int sargP[NB * NM];
    if (tid < NB * NM) {
        float v; unsigned ix;
        sdec(g_colkeyP[tid >> 5][tid & 31], v, ix);
        smaxP[tid] = v; sargP[tid] = (int)ix;
    }
    __syncthreads();

    // ---------------- Phase 4: sparse corrections only ----------------
    {
        int nitems = g_listCount;
        for (int i = gtid; i < nitems; i += GSZ) {
            int code = g_list[i];
            int a = code & (NA - 1);
            int img = (code >> 14) & 1;
            int pos = (code >> 15) & 1;
            int jm = (code >> 16) & 31;
            int jb = img << 5;
            const float* crow = cls + ((size_t)img * NA + a) * NC;
            float cc = 0.0f, rr = 0.0f;
            if (!pos) {
                float s = 0.0f;
#pragma unroll
                for (int c = 0; c < NC; c++) s += baseterm(crow[c]);
                cc = -s;
            } else {
                float mw = -1e30f;
                const float4* mrow = (const float4*)g_md[img][a];
#pragma unroll
                for (int c = 0; c < 8; c++) {
                    float4 m = mrow[c];
                    float mv[4] = {m.x, m.y, m.z, m.w};
#pragma unroll
                    for (int k = 0; k < 4; k++) {
                        int j = c * 4 + k;
                        float md = mv[k];
                        bool pm = (md >= 0.5f) || (sargP[jb + j] == a);
                        float comp = pm ? (1.0f - smaxP[jb + j]) : md;
                        mw = fmaxf(mw, comp + md);
                    }
                }
                const float* gt = ann + (size_t)(img * NM + jm) * 6;
                int lab = (int)gt[5];
                float xl = fminf(fmaxf(crow[lab], 0.0001f), 1.0f - 0.0001f);
                float posterm = 0.25f * (1.0f - xl) * (1.0f - xl) * (-__logf(xl + 1e-6f)) * (mw + 1.0f);
                cc = posterm - baseterm(crow[lab]);
                const float* ap = anc + (size_t)(img * NA + a) * 5;
                const float* rg = reg + (size_t)(img * NA + a) * 5;
                float tv[5];
                tv[0] = (gt[0] - ap[0]) / ap[2];
                tv[1] = (gt[1] - ap[1]) / ap[3];
                tv[2] = __logf(fmaxf(gt[2], 1.0f) / ap[2]);
                tv[3] = __logf(fmaxf(gt[3], 1.0f) / ap[3]);
                tv[4] = __tanf(gt[4] * (PI_F / 180.0f)) - __tanf(ap[4] * (PI_F / 180.0f));
                const float BETA = (float)(1.0 / 9.0);
#pragma unroll
                for (int k = 0; k < 5; k++) {
                    float diff = fabsf(rg[k] - tv[k]);
                    float sl = (diff < BETA) ? (0.5f * diff * diff / BETA) : (diff - 0.5f * BETA);
                    rr += sl * mw;
                }
            }
            if (img == 0) { cs0 += cc; rs0 += rr; } else { cs1 += cc; rs1 += rr; }
        }
    }

    // ---------------- block reduction + ticket finalize ----------------
    cs0 = warp_sum_f(cs0); cs1 = warp_sum_f(cs1);
    rs0 = warp_sum_f(rs0); rs1 = warp_sum_f(rs1);
    __shared__ float sc0[16], sc1[16], sr0[16], sr1[16];
    int warp = tid >> 5;
    if (lane == 0) { sc0[warp] = cs0; sc1[warp] = cs1; sr0[warp] = rs0; sr1[warp] = rs1; }
    __syncthreads();
    __shared__ bool lastf;
    if (tid == 0) {
        double c0 = 0.0, c1 = 0.0, r0 = 0.0, r1 = 0.0;
#pragma unroll
        for (int k = 0; k < 16; k++) {
            c0 += (double)sc0[k]; c1 += (double)sc1[k];
            r0 += (double)sr0[k]; r1 += (double)sr1[k];
        }
        if (c0 != 0.0) atomicAdd(&g_cls_sum[0], c0);
        if (c1 != 0.0) atomicAdd(&g_cls_sum[1], c1);
        if (r0 != 0.0) atomicAdd(&g_reg_sum[0], r0);
        if (r1 != 0.0) atomicAdd(&g_reg_sum[1], r1);
        __threadfence();
        unsigned tk = atomicAdd(&g_ticket, 1u);
        lastf = (tk == (unsigned)(NBLK - 1));
    }
    __syncthreads();
    if (lastf) {
        if (tid < NB * NM) {
            g_colkeyF[tid >> 5][tid & 31] = 0;
            g_colkeyP[tid >> 5][tid & 31] = NEGK;
        }
        if (tid == 64) g_listCount = 0;
        if (tid == 65) g_ticket = 0;
        if (tid == 66) { g_barCnt[0] = 0; g_barCnt[1] = 0; g_barCnt[2] = 0; }
        if (tid == 0) {
            double lc = 0.0, lr = 0.0;
#pragma unroll
            for (int i2 = 0; i2 < NB; i2++) {
                int np = g_numpos[i2];
                lc += g_cls_sum[i2] / fmax((double)np, 1.0);
                if (np > 0) lr += g_reg_sum[i2] / (double)(np * 5);
                g_cls_sum[i2] = 0.0; g_reg_sum[i2] = 0.0; g_numpos[i2] = 0;
            }
            out[0] = (float)(lc / (double)NB);
            out[1] = (float)(lr / (double)NB);
        }
    }
}

// ---------------- launcher: ONE kernel ----------------
extern "C" void kernel_launch(void* const* d_in, const int* in_sizes, int n_in,
                              void* d_out, int out_size) {
    const float* cls  = (const float*)d_in[0];
    const float* reg  = (const float*)d_in[1];
    const float* anc  = (const float*)d_in[2];
    const float* ranc = (const float*)d_in[3];
    const float* ann  = (const float*)d_in[4];
    float* out = (float*)d_out;

    k_all<<<NBLK, NTHR>>>(cls, reg, anc, ranc, ann, out);
}

// round 13
// speedup vs baseline: 1.5681x; 1.1896x over previous
#include <cuda_runtime.h>
#include <math.h>
#include <stdint.h>

#define NB 2
#define NA 16384
#define NM 32
#define NC 15
#define PI_F 3.14159265358979323846f
#define NBLK 148
#define NTHR 512
#define GSZ (NBLK * NTHR)

typedef long long ll;

#define NEGK (-9223372036854775807ll - 1ll)
#define N4 NEGK, NEGK, NEGK, NEGK
#define N32 N4, N4, N4, N4, N4, N4, N4, N4

// ---------------- persistent scratch (zero-init; finalize restores all state) --------
__device__ float  g_md[NB][NA][NM];
__device__ ll     g_rowkey[NB][NA];                    // identity 0; reset in phase 3
__device__ ll     g_colkeyF[NB][NM];                   // identity 0; reset by finalize
__device__ ll     g_colkeyP[NB][NM] = {{N32}, {N32}};  // identity NEGK; reset by finalize
__device__ int    g_pairs[2 * NB * NA * NM];
__device__ int    g_pairCount;                         // reset in phase 3
__device__ int    g_list[NB * NA];                     // POS anchors only
__device__ int    g_listCount;                         // reset by finalize
__device__ double g_cls_sum[NB];                       // reset by finalize
__device__ double g_reg_sum[NB];
__device__ int    g_numpos[NB];
__device__ unsigned g_ticket;                          // reset by finalize
__device__ unsigned g_barCnt[3];                       // reset by finalize

__device__ __forceinline__ ll spack(float v, unsigned idx) {
    return (ll)((unsigned long long)__float_as_uint(v) << 32) - (ll)idx;
}
__device__ __forceinline__ void sdec(ll k, float& v, unsigned& idx) {
    unsigned lo = (unsigned)(k & 0xFFFFFFFFll);
    idx = (unsigned)(-(int)lo);
    unsigned vb = (unsigned)(((unsigned long long)(k + (ll)idx)) >> 32);
    v = __uint_as_float(vb);
}

__device__ __forceinline__ float warp_sum_f(float v) {
#pragma unroll
    for (int off = 16; off > 0; off >>= 1) v += __shfl_xor_sync(0xffffffffu, v, off);
    return v;
}

__device__ __forceinline__ float baseterm(float xr) {
    float x = fminf(fmaxf(xr, 0.0001f), 1.0f - 0.0001f);
    return 0.75f * x * x * (-__logf(1.0f - x + 1e-6f));
}

// grid barrier: pure busy-spin; reset by finalize.
__device__ __forceinline__ void grid_barrier(int k) {
    __syncthreads();
    if (threadIdx.x == 0) {
        __threadfence();
        atomicAdd(&g_barCnt[k], 1u);
        while (*(volatile unsigned*)&g_barCnt[k] < (unsigned)NBLK) {}
        __threadfence();
    }
    __syncthreads();
}

// Sutherland-Hodgman on centered f32 coordinates; float2 slots, exact cap 8.
__device__ float quad_inter_area_f(const float* ax, const float* ay,
                                   const float* bx, const float* by) {
    float2 p[8], q[8];
    int n = 4;
#pragma unroll
    for (int i = 0; i < 4; i++) p[i] = make_float2(ax[i], ay[i]);
    for (int e = 0; e < 4; e++) {
        float x0 = bx[e], y0 = by[e];
        int e2 = (e + 1) & 3;
        float dx = bx[e2] - x0, dy = by[e2] - y0;
        int m = 0;
        float2 prev = p[n - 1];
        float dprev = dx * (prev.y - y0) - dy * (prev.x - x0);
        for (int i = 0; i < n; i++) {
            float2 cur = p[i];
            float dc = dx * (cur.y - y0) - dy * (cur.x - x0);
            bool inc = (dc >= 0.0f), inp = (dprev >= 0.0f);
            if (inc != inp) {
                float t = dprev / (dprev - dc);
                q[m] = make_float2(prev.x + t * (cur.x - prev.x),
                                   prev.y + t * (cur.y - prev.y));
                m++;
            }
            if (inc) { q[m] = cur; m++; }
            dprev = dc; prev = cur;
        }
        n = m;
        if (n == 0) return 0.0f;
        for (int i = 0; i < n; i++) p[i] = q[i];
    }
    if (n < 3) return 0.0f;
    float s = 0.0f;
    float2 pp = p[n - 1];
    for (int i = 0; i < n; i++) {
        s += pp.x * p[i].y - p[i].x * pp.y;
        pp = p[i];
    }
    return 0.5f * fabsf(s);
}

// gate test: FMA compare with exact-division fallback in the ambiguous band
__device__ __forceinline__ bool gate(float inter, float denom) {
    float lhs = inter * 10.0f;
    bool f = (lhs >= denom);
    if (fabsf(lhs - denom) < 1e-4f * denom) f = (inter / denom >= 0.1f);
    return f;
}

// ================ the single persistent kernel ================
__global__ void __launch_bounds__(NTHR, 1) k_all(const float* __restrict__ cls,
                                                 const float* __restrict__ reg,
                                                 const float* __restrict__ anc,
                                                 const float* __restrict__ ranc,
                                                 const float* __restrict__ ann,
                                                 float* __restrict__ out) {
    int tid = threadIdx.x;
    int lane = tid & 31;
    int gtid = blockIdx.x * NTHR + tid;

    // loss accumulators live across all phases
    float cs0 = 0.0f, cs1 = 0.0f, rs0 = 0.0f, rs1 = 0.0f;
    const float4* c4 = (const float4*)cls;
    const int HALF = NA * NC / 4;  // 61440 float4 per image

    __shared__ float sgx[NB * NM][4], sgy[NB * NM][4], sgar[NB * NM];
    __shared__ float sqx1[NB * NM], sqy1[NB * NM], sqx2[NB * NM], sqy2[NB * NM], sqar[NB * NM];
    __shared__ ll scol[NB * NM];

    if (tid < NB * NM) {
        int img = tid >> 5, j = tid & 31;
        const float* g = ann + (size_t)(img * NM + j) * 6;
        float cx = g[0], cy = g[1], w = g[2], h = g[3];
        float th = g[4] * (PI_F / 180.0f);
        float sn, cs;
        sincosf(th, &sn, &cs);   // precise: only 64 calls
        const float lx[4] = {-0.5f, 0.5f, 0.5f, -0.5f};
        const float ly[4] = {-0.5f, -0.5f, 0.5f, 0.5f};
#pragma unroll
        for (int k = 0; k < 4; k++) {
            float dx = w * lx[k], dy = h * ly[k];
            sgx[tid][k] = cx + dx * cs - dy * sn;
            sgy[tid][k] = cy + dx * sn + dy * cs;
        }
        sgar[tid] = w * h;
        float s = fmaxf(w, h) * 0.5f;
        sqx1[tid] = cx - s; sqy1[tid] = cy - s;
        sqx2[tid] = cx + s; sqy2[tid] = cy + s;
        sqar[tid] = (2.0f * s) * (2.0f * s);
        scol[tid] = 0;
    }
    __syncthreads();

    // -------- Phase 1: filter (half-row per thread) + dense base-sum iteration 0 ------
    if (gtid < NB * NA * 2) {
        int half = gtid & 1;
        int a = (gtid >> 1) & (NA - 1);
        int img = gtid >> 15;
        int aidx = img * NA + a;
        const float* p = anc + (size_t)aidx * 5;
        const float* q = ranc + (size_t)aidx * 5;
        float s0 = fmaxf(p[2], p[3]) * 0.5f;
        float ax1 = p[0] - s0, ay1 = p[1] - s0, ax2 = p[0] + s0, ay2 = p[1] + s0;
        float aar = (ax2 - ax1) * (ay2 - ay1);
        float s1 = fmaxf(q[2], q[3]) * 0.5f;
        float rx1 = q[0] - s1, ry1 = q[1] - s1, rx2 = q[0] + s1, ry2 = q[1] + s1;
        float rar = (rx2 - rx1) * (ry2 - ry1);
        int jb = (img << 5) + half * 16;

        int m = 0;   // number of gated (a,j) — each emits TWO entries
        unsigned fbits0 = 0, fbits1 = 0;
#pragma unroll
        for (int jj = 0; jj < 16; jj++) {
            float gx1 = sqx1[jb + jj], gy1 = sqy1[jb + jj];
            float gx2 = sqx2[jb + jj], gy2 = sqy2[jb + jj], gar = sqar[jb + jj];
            float wx = fmaxf(fminf(ax2, gx2) - fmaxf(ax1, gx1), 0.0f);
            float wy = fmaxf(fminf(ay2, gy2) - fmaxf(ay1, gy1), 0.0f);
            float i0 = wx * wy;
            bool f0 = gate(i0, aar + gar - i0 + 1e-8f);
            wx = fmaxf(fminf(rx2, gx2) - fmaxf(rx1, gx1), 0.0f);
            wy = fmaxf(fminf(ry2, gy2) - fmaxf(ry1, gy1), 0.0f);
            float i1 = wx * wy;
            bool f1 = gate(i1, rar + gar - i1 + 1e-8f);
            fbits0 |= ((unsigned)f0) << jj;
            fbits1 |= ((unsigned)f1) << jj;
            m += (int)(f0 | f1);
        }
        int incl = m;
#pragma unroll
        for (int off = 1; off < 32; off <<= 1) {
            int nn = __shfl_up_sync(0xffffffffu, incl, off);
            if (lane >= off) incl += nn;
        }
        int total = __shfl_sync(0xffffffffu, incl, 31);
        int base = 0;
        if (lane == 0 && total > 0) base = atomicAdd(&g_pairCount, 2 * total);
        base = __shfl_sync(0xffffffffu, base, 0);
        int off0 = base + 2 * (incl - m);
        unsigned both = fbits0 | fbits1;
        while (both) {
            int jj = __ffs(both) - 1;
            both &= both - 1;
            int j = half * 16 + jj;
            int f0 = (fbits0 >> jj) & 1, f1 = (fbits1 >> jj) & 1;
            int common = (img << 21) | (a << 7) | (j << 2);
            g_pairs[off0++] = common | (0 << 1) | f0;   // phase 0, do-clip = f0
            g_pairs[off0++] = common | (1 << 1) | f1;   // phase 1, do-clip = f1
        }
    }
    // dense base-sum, iteration 0
    {
        int i = gtid;
        if (i < 2 * HALF) {
            float4 v = c4[i];
            float s = baseterm(v.x) + baseterm(v.y) + baseterm(v.z) + baseterm(v.w);
            if (i < HALF) cs0 += s; else cs1 += s;
        }
    }

    grid_barrier(0);

    // -------- Phase 2: heavy clip, ONE quad per lane; lane pairs combine via shfl ------
    {
        int total = g_pairCount;
        int rounds = (total + GSZ - 1) / GSZ;
        const float lx[4] = {-0.5f, 0.5f, 0.5f, -0.5f};
        const float ly[4] = {-0.5f, -0.5f, 0.5f, 0.5f};
        for (int r = 0; r < rounds; r++) {
            int idx = gtid + r * GSZ;
            bool active = (idx < total);
            float iou = 0.0f;
            int code = 0;
            if (active) {
                code = g_pairs[idx];
                int doClip = code & 1;
                int ph = (code >> 1) & 1;
                int j = (code >> 2) & 31;
                int a = (code >> 7) & (NA - 1);
                int img = (code >> 21) & 1;
                if (doClip) {
                    const float* pp = (ph ? ranc : anc) + (size_t)(img * NA + a) * 5;
                    float cx = pp[0], cy = pp[1], w = pp[2], h = pp[3];
                    float th = pp[4] * (PI_F / 180.0f);
                    float sn, cs;
                    __sincosf(th, &sn, &cs);
                    int gj = (img << 5) + j;
                    float AX[4], AY[4], BX[4], BY[4];
#pragma unroll
                    for (int k = 0; k < 4; k++) {
                        float dx = w * lx[k], dy = h * ly[k];
                        AX[k] = dx * cs - dy * sn;
                        AY[k] = dx * sn + dy * cs;
                        BX[k] = sgx[gj][k] - cx;
                        BY[k] = sgy[gj][k] - cy;
                    }
                    float inter = quad_inter_area_f(AX, AY, BX, BY);
                    iou = inter / (w * h + sgar[gj] - inter + 1e-8f);
                }
            }
            // combine: even lane holds phase0 (bf), odd lane phase1 (af)
            float other = __shfl_xor_sync(0xffffffffu, iou, 1);
            if (active && ((idx & 1) == 0)) {
                float bf = iou, af = other;
                int j = (code >> 2) & 31;
                int a = (code >> 7) & (NA - 1);
                int img = (code >> 21) & 1;
                int gj = (img << 5) + j;
                float md = fabsf(bf + 0.5f * af - fabsf(af - bf));
                g_md[img][a][j] = md;
                atomicMax(&g_rowkey[img][a], spack(md, (unsigned)j));
                if (md > 0.0f) atomicMax(&scol[gj], spack(md, (unsigned)a));
            }
        }
        // dense base-sum, iteration 1 (overlaps clip stalls)
        {
            int i = gtid + GSZ;
            if (i < 2 * HALF) {
                float4 v = c4[i];
                float s = baseterm(v.x) + baseterm(v.y) + baseterm(v.z) + baseterm(v.w);
                if (i < HALF) cs0 += s; else cs1 += s;
            }
        }
        __syncthreads();
        if (tid < NB * NM && scol[tid] > 0)
            atomicMax(&g_colkeyF[tid >> 5][tid & 31], scol[tid]);
    }

    grid_barrier(1);

    // ------- Phase 3: colmax + force + POS compaction + inline ignore-band corrections -
    __shared__ int sforce[NB * NM];
    __shared__ ll scolp[NB * NM];
    __shared__ int snp[NB];
    if (tid < NB * NM) {
        float v; unsigned ix;
        sdec(g_colkeyF[tid >> 5][tid & 31], v, ix);
        sforce[tid] = (v < 0.5f) ? (int)ix : -1;
        scolp[tid] = NEGK;
    }
    if (tid == 128) { snp[0] = 0; snp[1] = 0; }
    if (gtid == GSZ - 1) g_pairCount = 0;  // consumed; reset for next replay
    __syncthreads();

    if (gtid < NB * NA) {
        int a = gtid & (NA - 1);
        int img = gtid >> 14;
        int jb = img << 5;
        ll rk = g_rowkey[img][a];
        if (rk != 0) g_rowkey[img][a] = 0;  // restore identity
        float iomax; unsigned jm;
        sdec(rk, iomax, jm);
        bool pos = (iomax >= 0.5f);
#pragma unroll
        for (int j = 0; j < NM; j++) pos |= (sforce[jb + j] == a);
        if (pos) {
            const float4* mrow = (const float4*)g_md[img][a];
#pragma unroll
            for (int c = 0; c < 8; c++) {
                float4 m = mrow[c];
                atomicMax(&scolp[jb + c * 4 + 0], spack(m.x, (unsigned)a));
                atomicMax(&scolp[jb + c * 4 + 1], spack(m.y, (unsigned)a));
                atomicMax(&scolp[jb + c * 4 + 2], spack(m.z, (unsigned)a));
                atomicMax(&scolp[jb + c * 4 + 3], spack(m.w, (unsigned)a));
            }
        } else if (iomax >= 0.4f) {
            // ignore band: tgt=-1 -> subtract base contribution (inline, overlapped)
            const float* crow = cls + ((size_t)img * NA + a) * NC;
            float s = 0.0f;
#pragma unroll
            for (int c = 0; c < NC; c++) s += baseterm(crow[c]);
            if (img == 0) cs0 -= s; else cs1 -= s;
        }
        unsigned mask = __ballot_sync(0xffffffffu, pos);
        if (mask) {
            int leader = __ffs(mask) - 1;
            int rank = __popc(mask & ((1u << lane) - 1));
            int base = 0;
            if (lane == leader) base = atomicAdd(&g_listCount, __popc(mask));
            base = __shfl_sync(0xffffffffu, base, leader);
            if (pos)
                g_list[base + rank] = a | (img << 14) | ((int)jm << 16);
        }
        if (lane == 0 && mask) atomicAdd(&snp[img], __popc(mask));
    }
    __syncthreads();
    if (tid < NB * NM && scolp[tid] != NEGK)
        atomicMax(&g_colkeyP[tid >> 5][tid & 31], scolp[tid]);
    if (tid == 128 && snp[0]) atomicAdd(&g_numpos[0], snp[0]);
    if (tid == 129 && snp[1]) atomicAdd(&g_numpos[1], snp[1]);

    grid_barrier(2);

    // ---- stage final colkeyP into shared (decoded) ----
    __shared__ float smaxP[NB * NM];
    __shared__ int sargP[NB * NM];
    if (tid < NB * NM) {
        float v; unsigned ix;
        sdec(g_colkeyP[tid >> 5][tid & 31], v, ix);
        smaxP[tid] = v; sargP[tid] = (int)ix;
    }
    __syncthreads();

    // ---------------- Phase 4: POS corrections only ----------------
    {
        int nitems = g_listCount;
        for (int i = gtid; i < nitems; i += GSZ) {
            int code = g_list[i];
            int a = code & (NA - 1);
            int img = (code >> 14) & 1;
            int jm = (code >> 16) & 31;
            int jb = img << 5;
            const float* crow = cls + ((size_t)img * NA + a) * NC;
            float cc, rr = 0.0f;
            float mw = -1e30f;
            const float4* mrow = (const float4*)g_md[img][a];
#pragma unroll
            for (int c = 0; c < 8; c++) {
                float4 m = mrow[c];
                float mv[4] = {m.x, m.y, m.z, m.w};
#pragma unroll
                for (int k = 0; k < 4; k++) {
                    int j = c * 4 + k;
                    float md = mv[k];
                    bool pm = (md >= 0.5f) || (sargP[jb + j] == a);
                    float comp = pm ? (1.0f - smaxP[jb + j]) : md;
                    mw = fmaxf(mw, comp + md);
                }
            }
            const float* gt = ann + (size_t)(img * NM + jm) * 6;
            int lab = (int)gt[5];
            float xl = fminf(fmaxf(crow[lab], 0.0001f), 1.0f - 0.0001f);
            float posterm = 0.25f * (1.0f - xl) * (1.0f - xl) * (-__logf(xl + 1e-6f)) * (mw + 1.0f);
            cc = posterm - baseterm(crow[lab]);
            const float* ap = anc + (size_t)(img * NA + a) * 5;
            const float* rg = reg + (size_t)(img * NA + a) * 5;
            float tv[5];
            tv[0] = (gt[0] - ap[0]) / ap[2];
            tv[1] = (gt[1] - ap[1]) / ap[3];
            tv[2] = __logf(fmaxf(gt[2], 1.0f) / ap[2]);
            tv[3] = __logf(fmaxf(gt[3], 1.0f) / ap[3]);
            tv[4] = __tanf(gt[4] * (PI_F / 180.0f)) - __tanf(ap[4] * (PI_F / 180.0f));
            const float BETA = (float)(1.0 / 9.0);
#pragma unroll
            for (int k = 0; k < 5; k++) {
                float diff = fabsf(rg[k] - tv[k]);
                float sl = (diff < BETA) ? (0.5f * diff * diff / BETA) : (diff - 0.5f * BETA);
                rr += sl * mw;
            }
            if (img == 0) { cs0 += cc; rs0 += rr; } else { cs1 += cc; rs1 += rr; }
        }
    }

    // ---------------- block reduction + ticket finalize ----------------
    cs0 = warp_sum_f(cs0); cs1 = warp_sum_f(cs1);
    rs0 = warp_sum_f(rs0); rs1 = warp_sum_f(rs1);
    __shared__ float sc0[16], sc1[16], sr0[16], sr1[16];
    int warp = tid >> 5;
    if (lane == 0) { sc0[warp] = cs0; sc1[warp] = cs1; sr0[warp] = rs0; sr1[warp] = rs1; }
    __syncthreads();
    __shared__ bool lastf;
    if (tid == 0) {
        double c0 = 0.0, c1 = 0.0, r0 = 0.0, r1 = 0.0;
#pragma unroll
        for (int k = 0; k < 16; k++) {
            c0 += (double)sc0[k]; c1 += (double)sc1[k];
            r0 += (double)sr0[k]; r1 += (double)sr1[k];
        }
        if (c0 != 0.0) atomicAdd(&g_cls_sum[0], c0);
        if (c1 != 0.0) atomicAdd(&g_cls_sum[1], c1);
        if (r0 != 0.0) atomicAdd(&g_reg_sum[0], r0);
        if (r1 != 0.0) atomicAdd(&g_reg_sum[1], r1);
        __threadfence();
        unsigned tk = atomicAdd(&g_ticket, 1u);
        lastf = (tk == (unsigned)(NBLK - 1));
    }
    __syncthreads();
    if (lastf) {
        if (tid < NB * NM) {
            g_colkeyF[tid >> 5][tid & 31] = 0;
            g_colkeyP[tid >> 5][tid & 31] = NEGK;
        }
        if (tid == 64) g_listCount = 0;
        if (tid == 65) g_ticket = 0;
        if (tid == 66) { g_barCnt[0] = 0; g_barCnt[1] = 0; g_barCnt[2] = 0; }
        if (tid == 0) {
            double lc = 0.0, lr = 0.0;
#pragma unroll
            for (int i2 = 0; i2 < NB; i2++) {
                int np = g_numpos[i2];
                lc += g_cls_sum[i2] / fmax((double)np, 1.0);
                if (np > 0) lr += g_reg_sum[i2] / (double)(np * 5);
                g_cls_sum[i2] = 0.0; g_reg_sum[i2] = 0.0; g_numpos[i2] = 0;
            }
            out[0] = (float)(lc / (double)NB);
            out[1] = (float)(lr / (double)NB);
        }
    }
}

// ---------------- launcher: ONE kernel ----------------
extern "C" void kernel_launch(void* const* d_in, const int* in_sizes, int n_in,
                              void* d_out, int out_size) {
    const float* cls  = (const float*)d_in[0];
    const float* reg  = (const float*)d_in[1];
    const float* anc  = (const float*)d_in[2];
    const float* ranc = (const float*)d_in[3];
    const float* ann  = (const float*)d_in[4];
    float* out = (float*)d_out;

    k_all<<<NBLK, NTHR>>>(cls, reg, anc, ranc, ann, out);
}

// round 14
// speedup vs baseline: 1.6988x; 1.0834x over previous
#include <cuda_runtime.h>
#include <math.h>
#include <stdint.h>

#define NB 2
#define NA 16384
#define NM 32
#define NC 15
#define PI_F 3.14159265358979323846f
#define NBLK 148
#define NTHR 512
#define GSZ (NBLK * NTHR)

typedef long long ll;

#define NEGK (-9223372036854775807ll - 1ll)
#define N4 NEGK, NEGK, NEGK, NEGK
#define N32 N4, N4, N4, N4, N4, N4, N4, N4

// ---------------- persistent scratch (zero-init; finalize restores all state) --------
__device__ float  g_md[NB][NA][NM];
__device__ ll     g_rowkey[NB][NA];                    // identity 0; reset in phase 3
__device__ ll     g_colkeyF[NB][NM];                   // identity 0; reset by finalize
__device__ ll     g_colkeyP[NB][NM] = {{N32}, {N32}};  // identity NEGK; reset by finalize
__device__ int    g_pairs[2 * NB * NA * NM];
__device__ int    g_pairCount;                         // reset in phase 3
__device__ int    g_list[NB * NA];                     // POS anchors only
__device__ int    g_listCount;                         // reset by finalize
__device__ double g_cls_sum[NB];                       // reset by finalize
__device__ double g_reg_sum[NB];
__device__ int    g_numpos[NB];
__device__ unsigned g_ticket;                          // reset by finalize
__device__ unsigned g_barCnt[3];                       // reset by finalize

__device__ __forceinline__ ll spack(float v, unsigned idx) {
    return (ll)((unsigned long long)__float_as_uint(v) << 32) - (ll)idx;
}
__device__ __forceinline__ void sdec(ll k, float& v, unsigned& idx) {
    unsigned lo = (unsigned)(k & 0xFFFFFFFFll);
    idx = (unsigned)(-(int)lo);
    unsigned vb = (unsigned)(((unsigned long long)(k + (ll)idx)) >> 32);
    v = __uint_as_float(vb);
}

__device__ __forceinline__ float warp_sum_f(float v) {
#pragma unroll
    for (int off = 16; off > 0; off >>= 1) v += __shfl_xor_sync(0xffffffffu, v, off);
    return v;
}

__device__ __forceinline__ float baseterm(float xr) {
    float x = fminf(fmaxf(xr, 0.0001f), 1.0f - 0.0001f);
    return 0.75f * x * x * (-__logf(1.0f - x + 1e-6f));
}

// grid barrier: pure busy-spin; reset by finalize.
__device__ __forceinline__ void grid_barrier(int k) {
    __syncthreads();
    if (threadIdx.x == 0) {
        __threadfence();
        atomicAdd(&g_barCnt[k], 1u);
        while (*(volatile unsigned*)&g_barCnt[k] < (unsigned)NBLK) {}
        __threadfence();
    }
    __syncthreads();
}

// Sutherland-Hodgman, unrolled passes: cross products computed in parallel,
// fast division for the intersection parameter.
__device__ float quad_inter_area_f(const float* ax, const float* ay,
                                   const float* bx, const float* by) {
    float2 p[8], q[8];
    int n = 4;
#pragma unroll
    for (int i = 0; i < 4; i++) p[i] = make_float2(ax[i], ay[i]);
#pragma unroll
    for (int e = 0; e < 4; e++) {
        float x0 = bx[e], y0 = by[e];
        int e2 = (e + 1) & 3;
        float dx = bx[e2] - x0, dy = by[e2] - y0;
        // parallel cross products
        float dv[8];
#pragma unroll
        for (int i = 0; i < 8; i++)
            if (i < n) dv[i] = dx * (p[i].y - y0) - dy * (p[i].x - x0);
        int m = 0;
#pragma unroll
        for (int i = 0; i < 8; i++) {
            if (i < n) {
                int ip = (i == 0) ? (n - 1) : (i - 1);
                float2 prev = p[ip], cur = p[i];
                float dp = dv[ip], dc = dv[i];
                bool inc = (dc >= 0.0f), inp = (dp >= 0.0f);
                if (inc != inp) {
                    float t = __fdividef(dp, dp - dc);
                    q[m] = make_float2(prev.x + t * (cur.x - prev.x),
                                       prev.y + t * (cur.y - prev.y));
                    m++;
                }
                if (inc) { q[m] = cur; m++; }
            }
        }
        n = m;
        if (n == 0) return 0.0f;
#pragma unroll
        for (int i = 0; i < 8; i++)
            if (i < n) p[i] = q[i];
    }
    if (n < 3) return 0.0f;
    float s = 0.0f;
    float2 pp = p[n - 1];
#pragma unroll
    for (int i = 0; i < 8; i++) {
        if (i < n) {
            s += pp.x * p[i].y - p[i].x * pp.y;
            pp = p[i];
        }
    }
    return 0.5f * fabsf(s);
}

// gate test: FMA compare with exact-division fallback in the ambiguous band
__device__ __forceinline__ bool gate(float inter, float denom) {
    float lhs = inter * 10.0f;
    bool f = (lhs >= denom);
    if (fabsf(lhs - denom) < 1e-4f * denom) f = (inter / denom >= 0.1f);
    return f;
}

// ================ the single persistent kernel ================
__global__ void __launch_bounds__(NTHR, 1) k_all(const float* __restrict__ cls,
                                                 const float* __restrict__ reg,
                                                 const float* __restrict__ anc,
                                                 const float* __restrict__ ranc,
                                                 const float* __restrict__ ann,
                                                 float* __restrict__ out) {
    int tid = threadIdx.x;
    int lane = tid & 31;
    int gtid = blockIdx.x * NTHR + tid;

    // loss accumulators live across all phases
    float cs0 = 0.0f, cs1 = 0.0f, rs0 = 0.0f, rs1 = 0.0f;
    const float4* c4 = (const float4*)cls;
    const int HALF = NA * NC / 4;  // 61440 float4 per image

    __shared__ float sgx[NB * NM][4], sgy[NB * NM][4], sgar[NB * NM];
    __shared__ float sqx1[NB * NM], sqy1[NB * NM], sqx2[NB * NM], sqy2[NB * NM], sqar[NB * NM];
    __shared__ ll scol[NB * NM];

    if (tid < NB * NM) {
        int img = tid >> 5, j = tid & 31;
        const float* g = ann + (size_t)(img * NM + j) * 6;
        float cx = g[0], cy = g[1], w = g[2], h = g[3];
        float th = g[4] * (PI_F / 180.0f);
        float sn, cs;
        sincosf(th, &sn, &cs);   // precise: only 64 calls
        const float lx[4] = {-0.5f, 0.5f, 0.5f, -0.5f};
        const float ly[4] = {-0.5f, -0.5f, 0.5f, 0.5f};
#pragma unroll
        for (int k = 0; k < 4; k++) {
            float dx = w * lx[k], dy = h * ly[k];
            sgx[tid][k] = cx + dx * cs - dy * sn;
            sgy[tid][k] = cy + dx * sn + dy * cs;
        }
        sgar[tid] = w * h;
        float s = fmaxf(w, h) * 0.5f;
        sqx1[tid] = cx - s; sqy1[tid] = cy - s;
        sqx2[tid] = cx + s; sqy2[tid] = cy + s;
        sqar[tid] = (2.0f * s) * (2.0f * s);
        scol[tid] = 0;
    }
    __syncthreads();

    // -------- Phase 1: filter (half-row per thread) + dense base-sum iteration 0 ------
    if (gtid < NB * NA * 2) {
        int half = gtid & 1;
        int a = (gtid >> 1) & (NA - 1);
        int img = gtid >> 15;
        int aidx = img * NA + a;
        const float* p = anc + (size_t)aidx * 5;
        const float* q = ranc + (size_t)aidx * 5;
        float s0 = fmaxf(p[2], p[3]) * 0.5f;
        float ax1 = p[0] - s0, ay1 = p[1] - s0, ax2 = p[0] + s0, ay2 = p[1] + s0;
        float aar = (ax2 - ax1) * (ay2 - ay1);
        float s1 = fmaxf(q[2], q[3]) * 0.5f;
        float rx1 = q[0] - s1, ry1 = q[1] - s1, rx2 = q[0] + s1, ry2 = q[1] + s1;
        float rar = (rx2 - rx1) * (ry2 - ry1);
        int jb = (img << 5) + half * 16;

        int m = 0;   // number of gated (a,j) — each emits TWO entries
        unsigned fbits0 = 0, fbits1 = 0;
#pragma unroll
        for (int jj = 0; jj < 16; jj++) {
            float gx1 = sqx1[jb + jj], gy1 = sqy1[jb + jj];
            float gx2 = sqx2[jb + jj], gy2 = sqy2[jb + jj], gar = sqar[jb + jj];
            float wx = fmaxf(fminf(ax2, gx2) - fmaxf(ax1, gx1), 0.0f);
            float wy = fmaxf(fminf(ay2, gy2) - fmaxf(ay1, gy1), 0.0f);
            float i0 = wx * wy;
            bool f0 = gate(i0, aar + gar - i0 + 1e-8f);
            wx = fmaxf(fminf(rx2, gx2) - fmaxf(rx1, gx1), 0.0f);
            wy = fmaxf(fminf(ry2, gy2) - fmaxf(ry1, gy1), 0.0f);
            float i1 = wx * wy;
            bool f1 = gate(i1, rar + gar - i1 + 1e-8f);
            fbits0 |= ((unsigned)f0) << jj;
            fbits1 |= ((unsigned)f1) << jj;
            m += (int)(f0 | f1);
        }
        int incl = m;
#pragma unroll
        for (int off = 1; off < 32; off <<= 1) {
            int nn = __shfl_up_sync(0xffffffffu, incl, off);
            if (lane >= off) incl += nn;
        }
        int total = __shfl_sync(0xffffffffu, incl, 31);
        int base = 0;
        if (lane == 0 && total > 0) base = atomicAdd(&g_pairCount, 2 * total);
        base = __shfl_sync(0xffffffffu, base, 0);
        int off0 = base + 2 * (incl - m);
        unsigned both = fbits0 | fbits1;
        while (both) {
            int jj = __ffs(both) - 1;
            both &= both - 1;
            int j = half * 16 + jj;
            int f0 = (fbits0 >> jj) & 1, f1 = (fbits1 >> jj) & 1;
            int common = (img << 21) | (a << 7) | (j << 2);
            g_pairs[off0++] = common | (0 << 1) | f0;   // phase 0, do-clip = f0
            g_pairs[off0++] = common | (1 << 1) | f1;   // phase 1, do-clip = f1
        }
    }
    // dense base-sum, iteration 0
    {
        int i = gtid;
        if (i < 2 * HALF) {
            float4 v = c4[i];
            float s = baseterm(v.x) + baseterm(v.y) + baseterm(v.z) + baseterm(v.w);
            if (i < HALF) cs0 += s; else cs1 += s;
        }
    }

    grid_barrier(0);

    // -------- Phase 2: heavy clip, ONE quad per lane; lane pairs combine via shfl ------
    {
        int total = g_pairCount;
        int rounds = (total + GSZ - 1) / GSZ;
        const float lx[4] = {-0.5f, 0.5f, 0.5f, -0.5f};
        const float ly[4] = {-0.5f, -0.5f, 0.5f, 0.5f};
        for (int r = 0; r < rounds; r++) {
            int idx = gtid + r * GSZ;
            bool active = (idx < total);
            float iou = 0.0f;
            int code = 0;
            if (active) {
                code = g_pairs[idx];
                int doClip = code & 1;
                int ph = (code >> 1) & 1;
                int j = (code >> 2) & 31;
                int a = (code >> 7) & (NA - 1);
                int img = (code >> 21) & 1;
                if (doClip) {
                    const float* pp = (ph ? ranc : anc) + (size_t)(img * NA + a) * 5;
                    float cx = pp[0], cy = pp[1], w = pp[2], h = pp[3];
                    float th = pp[4] * (PI_F / 180.0f);
                    float sn, cs;
                    __sincosf(th, &sn, &cs);
                    int gj = (img << 5) + j;
                    float AX[4], AY[4], BX[4], BY[4];
#pragma unroll
                    for (int k = 0; k < 4; k++) {
                        float dx = w * lx[k], dy = h * ly[k];
                        AX[k] = dx * cs - dy * sn;
                        AY[k] = dx * sn + dy * cs;
                        BX[k] = sgx[gj][k] - cx;
                        BY[k] = sgy[gj][k] - cy;
                    }
                    float inter = quad_inter_area_f(AX, AY, BX, BY);
                    iou = __fdividef(inter, w * h + sgar[gj] - inter + 1e-8f);
                }
            }
            // combine: even lane holds phase0 (bf), odd lane phase1 (af)
            float other = __shfl_xor_sync(0xffffffffu, iou, 1);
            if (active && ((idx & 1) == 0)) {
                float bf = iou, af = other;
                int j = (code >> 2) & 31;
                int a = (code >> 7) & (NA - 1);
                int img = (code >> 21) & 1;
                int gj = (img << 5) + j;
                float md = fabsf(bf + 0.5f * af - fabsf(af - bf));
                g_md[img][a][j] = md;
                atomicMax(&g_rowkey[img][a], spack(md, (unsigned)j));
                if (md > 0.0f) atomicMax(&scol[gj], spack(md, (unsigned)a));
            }
        }
        // dense base-sum, iteration 1 (overlaps clip stalls)
        {
            int i = gtid + GSZ;
            if (i < 2 * HALF) {
                float4 v = c4[i];
                float s = baseterm(v.x) + baseterm(v.y) + baseterm(v.z) + baseterm(v.w);
                if (i < HALF) cs0 += s; else cs1 += s;
            }
        }
        __syncthreads();
        if (tid < NB * NM && scol[tid] > 0)
            atomicMax(&g_colkeyF[tid >> 5][tid & 31], scol[tid]);
    }

    grid_barrier(1);

    // ------- Phase 3: colmax + force + POS compaction + inline ignore-band corrections -
    __shared__ int sforce[NB * NM];
    __shared__ ll scolp[NB * NM];
    __shared__ int snp[NB];
    if (tid < NB * NM) {
        float v; unsigned ix;
        sdec(g_colkeyF[tid >> 5][tid & 31], v, ix);
        sforce[tid] = (v < 0.5f) ? (int)ix : -1;
        scolp[tid] = NEGK;
    }
    if (tid == 128) { snp[0] = 0; snp[1] = 0; }
    if (gtid == GSZ - 1) g_pairCount = 0;  // consumed; reset for next replay
    __syncthreads();

    if (gtid < NB * NA) {
        int a = gtid & (NA - 1);
        int img = gtid >> 14;
        int jb = img << 5;
        ll rk = g_rowkey[img][a];
        if (rk != 0) g_rowkey[img][a] = 0;  // restore identity
        float iomax; unsigned jm;
        sdec(rk, iomax, jm);
        bool pos = (iomax >= 0.5f);
#pragma unroll
        for (int j = 0; j < NM; j++) pos |= (sforce[jb + j] == a);
        if (pos) {
            const float4* mrow = (const float4*)g_md[img][a];
#pragma unroll
            for (int c = 0; c < 8; c++) {
                float4 m = mrow[c];
                atomicMax(&scolp[jb + c * 4 + 0], spack(m.x, (unsigned)a));
                atomicMax(&scolp[jb + c * 4 + 1], spack(m.y, (unsigned)a));
                atomicMax(&scolp[jb + c * 4 + 2], spack(m.z, (unsigned)a));
                atomicMax(&scolp[jb + c * 4 + 3], spack(m.w, (unsigned)a));
            }
        } else if (iomax >= 0.4f) {
            // ignore band: tgt=-1 -> subtract base contribution (inline, overlapped)
            const float* crow = cls + ((size_t)img * NA + a) * NC;
            float s = 0.0f;
#pragma unroll
            for (int c = 0; c < NC; c++) s += baseterm(crow[c]);
            if (img == 0) cs0 -= s; else cs1 -= s;
        }
        unsigned mask = __ballot_sync(0xffffffffu, pos);
        if (mask) {
            int leader = __ffs(mask) - 1;
            int rank = __popc(mask & ((1u << lane) - 1));
            int base = 0;
            if (lane == leader) base = atomicAdd(&g_listCount, __popc(mask));
            base = __shfl_sync(0xffffffffu, base, leader);
            if (pos)
                g_list[base + rank] = a | (img << 14) | ((int)jm << 16);
        }
        if (lane == 0 && mask) atomicAdd(&snp[img], __popc(mask));
    }
    __syncthreads();
    if (tid < NB * NM && scolp[tid] != NEGK)
        atomicMax(&g_colkeyP[tid >> 5][tid & 31], scolp[tid]);
    if (tid == 128 && snp[0]) atomicAdd(&g_numpos[0], snp[0]);
    if (tid == 129 && snp[1]) atomicAdd(&g_numpos[1], snp[1]);

    grid_barrier(2);

    // ---- stage final colkeyP into shared (decoded) ----
    __shared__ float smaxP[NB * NM];
    __shared__ int sargP[NB * NM];
    if (tid < NB * NM) {
        float v; unsigned ix;
        sdec(g_colkeyP[tid >> 5][tid & 31], v, ix);
        smaxP[tid] = v; sargP[tid] = (int)ix;
    }
    __syncthreads();

    // ---------------- Phase 4: POS corrections only ----------------
    {
        int nitems = g_listCount;
        for (int i = gtid; i < nitems; i += GSZ) {
            int code = g_list[i];
            int a = code & (NA - 1);
            int img = (code >> 14) & 1;
            int jm = (code >> 16) & 31;
            int jb = img << 5;
            const float* crow = cls + ((size_t)img * NA + a) * NC;
            float cc, rr = 0.0f;
            float mw = -1e30f;
            const float4* mrow = (const float4*)g_md[img][a];
#pragma unroll
            for (int c = 0; c < 8; c++) {
                float4 m = mrow[c];
                float mv[4] = {m.x, m.y, m.z, m.w};
#pragma unroll
                for (int k = 0; k < 4; k++) {
                    int j = c * 4 + k;
                    float md = mv[k];
                    bool pm = (md >= 0.5f) || (sargP[jb + j] == a);
                    float comp = pm ? (1.0f - smaxP[jb + j]) : md;
                    mw = fmaxf(mw, comp + md);
                }
            }
            const float* gt = ann + (size_t)(img * NM + jm) * 6;
            int lab = (int)gt[5];
            float xl = fminf(fmaxf(crow[lab], 0.0001f), 1.0f - 0.0001f);
            float posterm = 0.25f * (1.0f - xl) * (1.0f - xl) * (-__logf(xl + 1e-6f)) * (mw + 1.0f);
            cc = posterm - baseterm(crow[lab]);
            const float* ap = anc + (size_t)(img * NA + a) * 5;
            const float* rg = reg + (size_t)(img * NA + a) * 5;
            float tv[5];
            tv[0] = (gt[0] - ap[0]) / ap[2];
            tv[1] = (gt[1] - ap[1]) / ap[3];
            tv[2] = __logf(fmaxf(gt[2], 1.0f) / ap[2]);
            tv[3] = __logf(fmaxf(gt[3], 1.0f) / ap[3]);
            tv[4] = __tanf(gt[4] * (PI_F / 180.0f)) - __tanf(ap[4] * (PI_F / 180.0f));
            const float BETA = (float)(1.0 / 9.0);
#pragma unroll
            for (int k = 0; k < 5; k++) {
                float diff = fabsf(rg[k] - tv[k]);
                float sl = (diff < BETA) ? (0.5f * diff * diff / BETA) : (diff - 0.5f * BETA);
                rr += sl * mw;
            }
            if (img == 0) { cs0 += cc; rs0 += rr; } else { cs1 += cc; rs1 += rr; }
        }
    }

    // ---------------- block reduction + ticket finalize ----------------
    cs0 = warp_sum_f(cs0); cs1 = warp_sum_f(cs1);
    rs0 = warp_sum_f(rs0); rs1 = warp_sum_f(rs1);
    __shared__ float sc0[16], sc1[16], sr0[16], sr1[16];
    int warp = tid >> 5;
    if (lane == 0) { sc0[warp] = cs0; sc1[warp] = cs1; sr0[warp] = rs0; sr1[warp] = rs1; }
    __syncthreads();
    __shared__ bool lastf;
    if (tid == 0) {
        double c0 = 0.0, c1 = 0.0, r0 = 0.0, r1 = 0.0;
#pragma unroll
        for (int k = 0; k < 16; k++) {
            c0 += (double)sc0[k]; c1 += (double)sc1[k];
            r0 += (double)sr0[k]; r1 += (double)sr1[k];
        }
        if (c0 != 0.0) atomicAdd(&g_cls_sum[0], c0);
        if (c1 != 0.0) atomicAdd(&g_cls_sum[1], c1);
        if (r0 != 0.0) atomicAdd(&g_reg_sum[0], r0);
        if (r1 != 0.0) atomicAdd(&g_reg_sum[1], r1);
        __threadfence();
        unsigned tk = atomicAdd(&g_ticket, 1u);
        lastf = (tk == (unsigned)(NBLK - 1));
    }
    __syncthreads();
    if (lastf) {
        if (tid < NB * NM) {
            g_colkeyF[tid >> 5][tid & 31] = 0;
            g_colkeyP[tid >> 5][tid & 31] = NEGK;
        }
        if (tid == 64) g_listCount = 0;
        if (tid == 65) g_ticket = 0;
        if (tid == 66) { g_barCnt[0] = 0; g_barCnt[1] = 0; g_barCnt[2] = 0; }
        if (tid == 0) {
            double lc = 0.0, lr = 0.0;
#pragma unroll
            for (int i2 = 0; i2 < NB; i2++) {
                int np = g_numpos[i2];
                lc += g_cls_sum[i2] / fmax((double)np, 1.0);
                if (np > 0) lr += g_reg_sum[i2] / (double)(np * 5);
                g_cls_sum[i2] = 0.0; g_reg_sum[i2] = 0.0; g_numpos[i2] = 0;
            }
            out[0] = (float)(lc / (double)NB);
            out[1] = (float)(lr / (double)NB);
        }
    }
}

// ---------------- launcher: ONE kernel ----------------
extern "C" void kernel_launch(void* const* d_in, const int* in_sizes, int n_in,
                              void* d_out, int out_size) {
    const float* cls  = (const float*)d_in[0];
    const float* reg  = (const float*)d_in[1];
    const float* anc  = (const float*)d_in[2];
    const float* ranc = (const float*)d_in[3];
    const float* ann  = (const float*)d_in[4];
    float* out = (float*)d_out;

    k_all<<<NBLK, NTHR>>>(cls, reg, anc, ranc, ann, out);
}

// round 15
// speedup vs baseline: 1.7174x; 1.0109x over previous
#include <cuda_runtime.h>
#include <math.h>
#include <stdint.h>

#define NB 2
#define NA 16384
#define NM 32
#define NC 15
#define PI_F 3.14159265358979323846f
#define NBLK 148
#define NTHR 512
#define GSZ (NBLK * NTHR)

typedef long long ll;

#define NEGK (-9223372036854775807ll - 1ll)
#define N4 NEGK, NEGK, NEGK, NEGK
#define N32 N4, N4, N4, N4, N4, N4, N4, N4

// ---------------- persistent scratch (zero-init; finalize restores all state) --------
__device__ float  g_md[NB][NA][NM];
__device__ ll     g_rowkey[NB][NA];                    // identity 0; reset in phase 3
__device__ ll     g_colkeyF[NB][NM];                   // identity 0; reset by finalize
__device__ ll     g_colkeyP[NB][NM] = {{N32}, {N32}};  // identity NEGK; reset by finalize
__device__ int    g_pairs[2 * NB * NA * NM];
__device__ int    g_pairCount;                         // reset in phase 3
__device__ int    g_list[NB * NA];                     // POS anchors only
__device__ int    g_listCount;                         // reset by finalize
__device__ double g_cls_sum[NB];                       // reset by finalize
__device__ double g_reg_sum[NB];
__device__ int    g_numpos[NB];
__device__ unsigned g_ticket;                          // reset by finalize
__device__ unsigned g_barCnt[3];                       // reset by finalize

__device__ __forceinline__ ll spack(float v, unsigned idx) {
    return (ll)((unsigned long long)__float_as_uint(v) << 32) - (ll)idx;
}
__device__ __forceinline__ void sdec(ll k, float& v, unsigned& idx) {
    unsigned lo = (unsigned)(k & 0xFFFFFFFFll);
    idx = (unsigned)(-(int)lo);
    unsigned vb = (unsigned)(((unsigned long long)(k + (ll)idx)) >> 32);
    v = __uint_as_float(vb);
}

__device__ __forceinline__ float warp_sum_f(float v) {
#pragma unroll
    for (int off = 16; off > 0; off >>= 1) v += __shfl_xor_sync(0xffffffffu, v, off);
    return v;
}

__device__ __forceinline__ float baseterm(float xr) {
    float x = fminf(fmaxf(xr, 0.0001f), 1.0f - 0.0001f);
    return 0.75f * x * x * (-__logf(1.0f - x + 1e-6f));
}

// grid barrier: pure busy-spin; reset by finalize.
__device__ __forceinline__ void grid_barrier(int k) {
    __syncthreads();
    if (threadIdx.x == 0) {
        __threadfence();
        atomicAdd(&g_barCnt[k], 1u);
        while (*(volatile unsigned*)&g_barCnt[k] < (unsigned)NBLK) {}
        __threadfence();
    }
    __syncthreads();
}

// Sutherland-Hodgman with PING-PONG buffers (no copy-back), carried prev/dprev,
// fast division. After 4 passes the result lands in buf0.
__device__ float quad_inter_area_f(const float* ax, const float* ay,
                                   const float* bx, const float* by) {
    float2 buf0[8], buf1[8];
    int n = 4;
#pragma unroll
    for (int i = 0; i < 4; i++) buf0[i] = make_float2(ax[i], ay[i]);
#pragma unroll
    for (int e = 0; e < 4; e++) {
        float2* src = (e & 1) ? buf1 : buf0;
        float2* dst = (e & 1) ? buf0 : buf1;
        float x0 = bx[e], y0 = by[e];
        int e2 = (e + 1) & 3;
        float dx = bx[e2] - x0, dy = by[e2] - y0;
        int m = 0;
        float2 prev = src[n - 1];
        float dprev = dx * (prev.y - y0) - dy * (prev.x - x0);
#pragma unroll
        for (int i = 0; i < 8; i++) {
            if (i < n) {
                float2 cur = src[i];
                float dc = dx * (cur.y - y0) - dy * (cur.x - x0);
                bool inc = (dc >= 0.0f), inp = (dprev >= 0.0f);
                if (inc != inp) {
                    float t = __fdividef(dprev, dprev - dc);
                    dst[m] = make_float2(prev.x + t * (cur.x - prev.x),
                                         prev.y + t * (cur.y - prev.y));
                    m++;
                }
                if (inc) { dst[m] = cur; m++; }
                dprev = dc; prev = cur;
            }
        }
        n = m;
        if (n == 0) return 0.0f;
    }
    if (n < 3) return 0.0f;
    // after e=3 the destination was buf0
    float s = 0.0f;
    float2 pp = buf0[n - 1];
#pragma unroll
    for (int i = 0; i < 8; i++) {
        if (i < n) {
            s += pp.x * buf0[i].y - buf0[i].x * pp.y;
            pp = buf0[i];
        }
    }
    return 0.5f * fabsf(s);
}

// gate test: FMA compare with exact-division fallback in the ambiguous band
__device__ __forceinline__ bool gate(float inter, float denom) {
    float lhs = inter * 10.0f;
    bool f = (lhs >= denom);
    if (fabsf(lhs - denom) < 1e-4f * denom) f = (inter / denom >= 0.1f);
    return f;
}

// ================ the single persistent kernel ================
__global__ void __launch_bounds__(NTHR, 1) k_all(const float* __restrict__ cls,
                                                 const float* __restrict__ reg,
                                                 const float* __restrict__ anc,
                                                 const float* __restrict__ ranc,
                                                 const float* __restrict__ ann,
                                                 float* __restrict__ out) {
    int tid = threadIdx.x;
    int lane = tid & 31;
    int gtid = blockIdx.x * NTHR + tid;

    // loss accumulators live across all phases
    float cs0 = 0.0f, cs1 = 0.0f, rs0 = 0.0f, rs1 = 0.0f;
    const float4* c4 = (const float4*)cls;
    const int HALF = NA * NC / 4;  // 61440 float4 per image

    __shared__ float sgx[NB * NM][4], sgy[NB * NM][4], sgar[NB * NM];
    __shared__ float sqx1[NB * NM], sqy1[NB * NM], sqx2[NB * NM], sqy2[NB * NM], sqar[NB * NM];
    __shared__ ll scol[NB * NM];

    if (tid < NB * NM) {
        int img = tid >> 5, j = tid & 31;
        const float* g = ann + (size_t)(img * NM + j) * 6;
        float cx = g[0], cy = g[1], w = g[2], h = g[3];
        float th = g[4] * (PI_F / 180.0f);
        float sn, cs;
        sincosf(th, &sn, &cs);   // precise: only 64 calls
        const float lx[4] = {-0.5f, 0.5f, 0.5f, -0.5f};
        const float ly[4] = {-0.5f, -0.5f, 0.5f, 0.5f};
#pragma unroll
        for (int k = 0; k < 4; k++) {
            float dx = w * lx[k], dy = h * ly[k];
            sgx[tid][k] = cx + dx * cs - dy * sn;
            sgy[tid][k] = cy + dx * sn + dy * cs;
        }
        sgar[tid] = w * h;
        float s = fmaxf(w, h) * 0.5f;
        sqx1[tid] = cx - s; sqy1[tid] = cy - s;
        sqx2[tid] = cx + s; sqy2[tid] = cy + s;
        sqar[tid] = (2.0f * s) * (2.0f * s);
        scol[tid] = 0;
    }
    __syncthreads();

    // -------- Phase 1: filter (half-row per thread) + dense base-sum iteration 0 ------
    if (gtid < NB * NA * 2) {
        int half = gtid & 1;
        int a = (gtid >> 1) & (NA - 1);
        int img = gtid >> 15;
        int aidx = img * NA + a;
        const float* p = anc + (size_t)aidx * 5;
        const float* q = ranc + (size_t)aidx * 5;
        float s0 = fmaxf(p[2], p[3]) * 0.5f;
        float ax1 = p[0] - s0, ay1 = p[1] - s0, ax2 = p[0] + s0, ay2 = p[1] + s0;
        float aar = (ax2 - ax1) * (ay2 - ay1);
        float s1 = fmaxf(q[2], q[3]) * 0.5f;
        float rx1 = q[0] - s1, ry1 = q[1] - s1, rx2 = q[0] + s1, ry2 = q[1] + s1;
        float rar = (rx2 - rx1) * (ry2 - ry1);
        int jb = (img << 5) + half * 16;

        int m = 0;   // number of gated (a,j) — each emits TWO entries
        unsigned fbits0 = 0, fbits1 = 0;
#pragma unroll
        for (int jj = 0; jj < 16; jj++) {
            float gx1 = sqx1[jb + jj], gy1 = sqy1[jb + jj];
            float gx2 = sqx2[jb + jj], gy2 = sqy2[jb + jj], gar = sqar[jb + jj];
            float wx = fmaxf(fminf(ax2, gx2) - fmaxf(ax1, gx1), 0.0f);
            float wy = fmaxf(fminf(ay2, gy2) - fmaxf(ay1, gy1), 0.0f);
            float i0 = wx * wy;
            bool f0 = gate(i0, aar + gar - i0 + 1e-8f);
            wx = fmaxf(fminf(rx2, gx2) - fmaxf(rx1, gx1), 0.0f);
            wy = fmaxf(fminf(ry2, gy2) - fmaxf(ry1, gy1), 0.0f);
            float i1 = wx * wy;
            bool f1 = gate(i1, rar + gar - i1 + 1e-8f);
            fbits0 |= ((unsigned)f0) << jj;
            fbits1 |= ((unsigned)f1) << jj;
            m += (int)(f0 | f1);
        }
        int incl = m;
#pragma unroll
        for (int off = 1; off < 32; off <<= 1) {
            int nn = __shfl_up_sync(0xffffffffu, incl, off);
            if (lane >= off) incl += nn;
        }
        int total = __shfl_sync(0xffffffffu, incl, 31);
        int base = 0;
        if (lane == 0 && total > 0) base = atomicAdd(&g_pairCount, 2 * total);
        base = __shfl_sync(0xffffffffu, base, 0);
        int off0 = base + 2 * (incl - m);
        unsigned both = fbits0 | fbits1;
        while (both) {
            int jj = __ffs(both) - 1;
            both &= both - 1;
            int j = half * 16 + jj;
            int f0 = (fbits0 >> jj) & 1, f1 = (fbits1 >> jj) & 1;
            int common = (img << 21) | (a << 7) | (j << 2);
            g_pairs[off0++] = common | (0 << 1) | f0;   // phase 0, do-clip = f0
            g_pairs[off0++] = common | (1 << 1) | f1;   // phase 1, do-clip = f1
        }
    }
    // dense base-sum, iteration 0
    {
        int i = gtid;
        if (i < 2 * HALF) {
            float4 v = c4[i];
            float s = baseterm(v.x) + baseterm(v.y) + baseterm(v.z) + baseterm(v.w);
            if (i < HALF) cs0 += s; else cs1 += s;
        }
    }

    grid_barrier(0);

    // -------- Phase 2: heavy clip, ONE quad per lane; lane pairs combine via shfl ------
    {
        int total = g_pairCount;
        int rounds = (total + GSZ - 1) / GSZ;
        const float lx[4] = {-0.5f, 0.5f, 0.5f, -0.5f};
        const float ly[4] = {-0.5f, -0.5f, 0.5f, 0.5f};
        for (int r = 0; r < rounds; r++) {
            int idx = gtid + r * GSZ;
            bool active = (idx < total);
            float iou = 0.0f;
            int code = 0;
            if (active) {
                code = g_pairs[idx];
                int doClip = code & 1;
                int ph = (code >> 1) & 1;
                int j = (code >> 2) & 31;
                int a = (code >> 7) & (NA - 1);
                int img = (code >> 21) & 1;
                if (doClip) {
                    const float* pp = (ph ? ranc : anc) + (size_t)(img * NA + a) * 5;
                    float cx = pp[0], cy = pp[1], w = pp[2], h = pp[3];
                    float th = pp[4] * (PI_F / 180.0f);
                    float sn, cs;
                    __sincosf(th, &sn, &cs);
                    int gj = (img << 5) + j;
                    float AX[4], AY[4], BX[4], BY[4];
#pragma unroll
                    for (int k = 0; k < 4; k++) {
                        float dx = w * lx[k], dy = h * ly[k];
                        AX[k] = dx * cs - dy * sn;
                        AY[k] = dx * sn + dy * cs;
                        BX[k] = sgx[gj][k] - cx;
                        BY[k] = sgy[gj][k] - cy;
                    }
                    float inter = quad_inter_area_f(AX, AY, BX, BY);
                    iou = __fdividef(inter, w * h + sgar[gj] - inter + 1e-8f);
                }
            }
            // combine: even lane holds phase0 (bf), odd lane phase1 (af)
            float other = __shfl_xor_sync(0xffffffffu, iou, 1);
            if (active && ((idx & 1) == 0)) {
                float bf = iou, af = other;
                int j = (code >> 2) & 31;
                int a = (code >> 7) & (NA - 1);
                int img = (code >> 21) & 1;
                int gj = (img << 5) + j;
                float md = fabsf(bf + 0.5f * af - fabsf(af - bf));
                g_md[img][a][j] = md;
                atomicMax(&g_rowkey[img][a], spack(md, (unsigned)j));
                if (md > 0.0f) atomicMax(&scol[gj], spack(md, (unsigned)a));
            }
        }
        // dense base-sum, iteration 1 (overlaps clip stalls)
        {
            int i = gtid + GSZ;
            if (i < 2 * HALF) {
                float4 v = c4[i];
                float s = baseterm(v.x) + baseterm(v.y) + baseterm(v.z) + baseterm(v.w);
                if (i < HALF) cs0 += s; else cs1 += s;
            }
        }
        __syncthreads();
        if (tid < NB * NM && scol[tid] > 0)
            atomicMax(&g_colkeyF[tid >> 5][tid & 31], scol[tid]);
    }

    grid_barrier(1);

    // ------- Phase 3: colmax + force + POS compaction + inline ignore-band corrections -
    __shared__ int sforce[NB * NM];
    __shared__ ll scolp[NB * NM];
    __shared__ int snp[NB];
    if (tid < NB * NM) {
        float v; unsigned ix;
        sdec(g_colkeyF[tid >> 5][tid & 31], v, ix);
        sforce[tid] = (v < 0.5f) ? (int)ix : -1;
        scolp[tid] = NEGK;
    }
    if (tid == 128) { snp[0] = 0; snp[1] = 0; }
    if (gtid == GSZ - 1) g_pairCount = 0;  // consumed; reset for next replay
    __syncthreads();

    if (gtid < NB * NA) {
        int a = gtid & (NA - 1);
        int img = gtid >> 14;
        int jb = img << 5;
        ll rk = g_rowkey[img][a];
        if (rk != 0) g_rowkey[img][a] = 0;  // restore identity
        float iomax; unsigned jm;
        sdec(rk, iomax, jm);
        bool pos = (iomax >= 0.5f);
#pragma unroll
        for (int j = 0; j < NM; j++) pos |= (sforce[jb + j] == a);
        if (pos) {
            const float4* mrow = (const float4*)g_md[img][a];
#pragma unroll
            for (int c = 0; c < 8; c++) {
                float4 m = mrow[c];
                atomicMax(&scolp[jb + c * 4 + 0], spack(m.x, (unsigned)a));
                atomicMax(&scolp[jb + c * 4 + 1], spack(m.y, (unsigned)a));
                atomicMax(&scolp[jb + c * 4 + 2], spack(m.z, (unsigned)a));
                atomicMax(&scolp[jb + c * 4 + 3], spack(m.w, (unsigned)a));
            }
        } else if (iomax >= 0.4f) {
            // ignore band: tgt=-1 -> subtract base contribution (inline, overlapped)
            const float* crow = cls + ((size_t)img * NA + a) * NC;
            float s = 0.0f;
#pragma unroll
            for (int c = 0; c < NC; c++) s += baseterm(crow[c]);
            if (img == 0) cs0 -= s; else cs1 -= s;
        }
        unsigned mask = __ballot_sync(0xffffffffu, pos);
        if (mask) {
            int leader = __ffs(mask) - 1;
            int rank = __popc(mask & ((1u << lane) - 1));
            int base = 0;
            if (lane == leader) base = atomicAdd(&g_listCount, __popc(mask));
            base = __shfl_sync(0xffffffffu, base, leader);
            if (pos)
                g_list[base + rank] = a | (img << 14) | ((int)jm << 16);
        }
        if (lane == 0 && mask) atomicAdd(&snp[img], __popc(mask));
    }
    __syncthreads();
    if (tid < NB * NM && scolp[tid] != NEGK)
        atomicMax(&g_colkeyP[tid >> 5][tid & 31], scolp[tid]);
    if (tid == 128 && snp[0]) atomicAdd(&g_numpos[0], snp[0]);
    if (tid == 129 && snp[1]) atomicAdd(&g_numpos[1], snp[1]);

    grid_barrier(2);

    // ---- stage final colkeyP into shared (decoded) ----
    __shared__ float smaxP[NB * NM];
    __shared__ int sargP[NB * NM];
    if (tid < NB * NM) {
        float v; unsigned ix;
        sdec(g_colkeyP[tid >> 5][tid & 31], v, ix);
        smaxP[tid] = v; sargP[tid] = (int)ix;
    }
    __syncthreads();

    // ---------------- Phase 4: POS corrections only ----------------
    {
        int nitems = g_listCount;
        for (int i = gtid; i < nitems; i += GSZ) {
            int code = g_list[i];
            int a = code & (NA - 1);
            int img = (code >> 14) & 1;
            int jm = (code >> 16) & 31;
            int jb = img << 5;
            const float* crow = cls + ((size_t)img * NA + a) * NC;
            float cc, rr = 0.0f;
            float mw = -1e30f;
            const float4* mrow = (const float4*)g_md[img][a];
#pragma unroll
            for (int c = 0; c < 8; c++) {
                float4 m = mrow[c];
                float mv[4] = {m.x, m.y, m.z, m.w};
#pragma unroll
                for (int k = 0; k < 4; k++) {
                    int j = c * 4 + k;
                    float md = mv[k];
                    bool pm = (md >= 0.5f) || (sargP[jb + j] == a);
                    float comp = pm ? (1.0f - smaxP[jb + j]) : md;
                    mw = fmaxf(mw, comp + md);
                }
            }
            const float* gt = ann + (size_t)(img * NM + jm) * 6;
            int lab = (int)gt[5];
            float xl = fminf(fmaxf(crow[lab], 0.0001f), 1.0f - 0.0001f);
            float posterm = 0.25f * (1.0f - xl) * (1.0f - xl) * (-__logf(xl + 1e-6f)) * (mw + 1.0f);
            cc = posterm - baseterm(crow[lab]);
            const float* ap = anc + (size_t)(img * NA + a) * 5;
            const float* rg = reg + (size_t)(img * NA + a) * 5;
            float tv[5];
            tv[0] = (gt[0] - ap[0]) / ap[2];
            tv[1] = (gt[1] - ap[1]) / ap[3];
            tv[2] = __logf(fmaxf(gt[2], 1.0f) / ap[2]);
            tv[3] = __logf(fmaxf(gt[3], 1.0f) / ap[3]);
            tv[4] = __tanf(gt[4] * (PI_F / 180.0f)) - __tanf(ap[4] * (PI_F / 180.0f));
            const float BETA = (float)(1.0 / 9.0);
#pragma unroll
            for (int k = 0; k < 5; k++) {
                float diff = fabsf(rg[k] - tv[k]);
                float sl = (diff < BETA) ? (0.5f * diff * diff / BETA) : (diff - 0.5f * BETA);
                rr += sl * mw;
            }
            if (img == 0) { cs0 += cc; rs0 += rr; } else { cs1 += cc; rs1 += rr; }
        }
    }

    // ---------------- block reduction + ticket finalize ----------------
    cs0 = warp_sum_f(cs0); cs1 = warp_sum_f(cs1);
    rs0 = warp_sum_f(rs0); rs1 = warp_sum_f(rs1);
    __shared__ float sc0[16], sc1[16], sr0[16], sr1[16];
    int warp = tid >> 5;
    if (lane == 0) { sc0[warp] = cs0; sc1[warp] = cs1; sr0[warp] = rs0; sr1[warp] = rs1; }
    __syncthreads();
    __shared__ bool lastf;
    if (tid == 0) {
        double c0 = 0.0, c1 = 0.0, r0 = 0.0, r1 = 0.0;
#pragma unroll
        for (int k = 0; k < 16; k++) {
            c0 += (double)sc0[k]; c1 += (double)sc1[k];
            r0 += (double)sr0[k]; r1 += (double)sr1[k];
        }
        if (c0 != 0.0) atomicAdd(&g_cls_sum[0], c0);
        if (c1 != 0.0) atomicAdd(&g_cls_sum[1], c1);
        if (r0 != 0.0) atomicAdd(&g_reg_sum[0], r0);
        if (r1 != 0.0) atomicAdd(&g_reg_sum[1], r1);
        __threadfence();
        unsigned tk = atomicAdd(&g_ticket, 1u);
        lastf = (tk == (unsigned)(NBLK - 1));
    }
    __syncthreads();
    if (lastf) {
        if (tid < NB * NM) {
            g_colkeyF[tid >> 5][tid & 31] = 0;
            g_colkeyP[tid >> 5][tid & 31] = NEGK;
        }
        if (tid == 64) g_listCount = 0;
        if (tid == 65) g_ticket = 0;
        if (tid == 66) { g_barCnt[0] = 0; g_barCnt[1] = 0; g_barCnt[2] = 0; }
        if (tid == 0) {
            double lc = 0.0, lr = 0.0;
#pragma unroll
            for (int i2 = 0; i2 < NB; i2++) {
                int np = g_numpos[i2];
                lc += g_cls_sum[i2] / fmax((double)np, 1.0);
                if (np > 0) lr += g_reg_sum[i2] / (double)(np * 5);
                g_cls_sum[i2] = 0.0; g_reg_sum[i2] = 0.0; g_numpos[i2] = 0;
            }
            out[0] = (float)(lc / (double)NB);
            out[1] = (float)(lr / (double)NB);
        }
    }
}

// ---------------- launcher: ONE kernel ----------------
extern "C" void kernel_launch(void* const* d_in, const int* in_sizes, int n_in,
                              void* d_out, int out_size) {
    const float* cls  = (const float*)d_in[0];
    const float* reg  = (const float*)d_in[1];
    const float* anc  = (const float*)d_in[2];
    const float* ranc = (const float*)d_in[3];
    const float* ann  = (const float*)d_in[4];
    float* out = (float*)d_out;

    k_all<<<NBLK, NTHR>>>(cls, reg, anc, ranc, ann, out);
}

// round 16
// speedup vs baseline: 1.7857x; 1.0398x over previous
#include <cuda_runtime.h>
#include <math.h>
#include <stdint.h>

#define NB 2
#define NA 16384
#define NM 32
#define NC 15
#define PI_F 3.14159265358979323846f
#define NBLK 148
#define NTHR 512
#define GSZ (NBLK * NTHR)

typedef long long ll;

#define NEGK (-9223372036854775807ll - 1ll)
#define N4 NEGK, NEGK, NEGK, NEGK
#define N32 N4, N4, N4, N4, N4, N4, N4, N4

// ---------------- persistent scratch (zero-init; finalize restores all state) --------
__device__ float  g_md[NB][NA][NM];
__device__ ll     g_rowkey[NB][NA];                    // identity 0; reset in phase 3
__device__ ll     g_colkeyF[NB][NM];                   // identity 0; reset by finalize
__device__ ll     g_colkeyP[NB][NM] = {{N32}, {N32}};  // identity NEGK; reset by finalize
__device__ int    g_pairs[2 * NB * NA * NM];
__device__ int    g_pairCount;                         // reset in phase 3
__device__ int    g_list[NB * NA];                     // POS anchors only
__device__ int    g_listCount;                         // reset by finalize
__device__ double g_cls_sum[NB];                       // reset by finalize
__device__ double g_reg_sum[NB];
__device__ int    g_numpos[NB];
__device__ unsigned g_ticket;                          // reset by finalize
__device__ unsigned g_barCnt[3];                       // reset by finalize

__device__ __forceinline__ ll spack(float v, unsigned idx) {
    return (ll)((unsigned long long)__float_as_uint(v) << 32) - (ll)idx;
}
__device__ __forceinline__ void sdec(ll k, float& v, unsigned& idx) {
    unsigned lo = (unsigned)(k & 0xFFFFFFFFll);
    idx = (unsigned)(-(int)lo);
    unsigned vb = (unsigned)(((unsigned long long)(k + (ll)idx)) >> 32);
    v = __uint_as_float(vb);
}

__device__ __forceinline__ float warp_sum_f(float v) {
#pragma unroll
    for (int off = 16; off > 0; off >>= 1) v += __shfl_xor_sync(0xffffffffu, v, off);
    return v;
}

__device__ __forceinline__ float baseterm(float xr) {
    float x = fminf(fmaxf(xr, 0.0001f), 1.0f - 0.0001f);
    return 0.75f * x * x * (-__logf(1.0f - x + 1e-6f));
}

// grid barrier: pure busy-spin; reset by finalize.
__device__ __forceinline__ void grid_barrier(int k) {
    __syncthreads();
    if (threadIdx.x == 0) {
        __threadfence();
        atomicAdd(&g_barCnt[k], 1u);
        while (*(volatile unsigned*)&g_barCnt[k] < (unsigned)NBLK) {}
        __threadfence();
    }
    __syncthreads();
}

// Sutherland-Hodgman with PING-PONG buffers (no copy-back), carried prev/dprev,
// fast division. After 4 passes the result lands in buf0.
__device__ float quad_inter_area_f(const float* ax, const float* ay,
                                   const float* bx, const float* by) {
    float2 buf0[8], buf1[8];
    int n = 4;
#pragma unroll
    for (int i = 0; i < 4; i++) buf0[i] = make_float2(ax[i], ay[i]);
#pragma unroll
    for (int e = 0; e < 4; e++) {
        float2* src = (e & 1) ? buf1 : buf0;
        float2* dst = (e & 1) ? buf0 : buf1;
        float x0 = bx[e], y0 = by[e];
        int e2 = (e + 1) & 3;
        float dx = bx[e2] - x0, dy = by[e2] - y0;
        int m = 0;
        float2 prev = src[n - 1];
        float dprev = dx * (prev.y - y0) - dy * (prev.x - x0);
#pragma unroll
        for (int i = 0; i < 8; i++) {
            if (i < n) {
                float2 cur = src[i];
                float dc = dx * (cur.y - y0) - dy * (cur.x - x0);
                bool inc = (dc >= 0.0f), inp = (dprev >= 0.0f);
                if (inc != inp) {
                    float t = __fdividef(dprev, dprev - dc);
                    dst[m] = make_float2(prev.x + t * (cur.x - prev.x),
                                         prev.y + t * (cur.y - prev.y));
                    m++;
                }
                if (inc) { dst[m] = cur; m++; }
                dprev = dc; prev = cur;
            }
        }
        n = m;
        if (n == 0) return 0.0f;
    }
    if (n < 3) return 0.0f;
    float s = 0.0f;
    float2 pp = buf0[n - 1];
#pragma unroll
    for (int i = 0; i < 8; i++) {
        if (i < n) {
            s += pp.x * buf0[i].y - buf0[i].x * pp.y;
            pp = buf0[i];
        }
    }
    return 0.5f * fabsf(s);
}

// gate test: FMA compare with exact-division fallback in the ambiguous band
__device__ __forceinline__ bool gate(float inter, float denom) {
    float lhs = inter * 10.0f;
    bool f = (lhs >= denom);
    if (fabsf(lhs - denom) < 1e-4f * denom) f = (inter / denom >= 0.1f);
    return f;
}

// ================ the single persistent kernel ================
__global__ void __launch_bounds__(NTHR, 1) k_all(const float* __restrict__ cls,
                                                 const float* __restrict__ reg,
                                                 const float* __restrict__ anc,
                                                 const float* __restrict__ ranc,
                                                 const float* __restrict__ ann,
                                                 float* __restrict__ out) {
    int tid = threadIdx.x;
    int lane = tid & 31;
    int gtid = blockIdx.x * NTHR + tid;

    // loss accumulators live across all phases
    float cs0 = 0.0f, cs1 = 0.0f, rs0 = 0.0f, rs1 = 0.0f;
    const float4* c4 = (const float4*)cls;
    const int HALF = NA * NC / 4;  // 61440 float4 per image

    __shared__ float sgx[NB * NM][4], sgy[NB * NM][4], sgar[NB * NM];
    __shared__ float sqx1[NB * NM], sqy1[NB * NM], sqx2[NB * NM], sqy2[NB * NM], sqar[NB * NM];
    __shared__ ll scol[NB * NM];

    if (tid < NB * NM) {
        int img = tid >> 5, j = tid & 31;
        const float* g = ann + (size_t)(img * NM + j) * 6;
        float cx = g[0], cy = g[1], w = g[2], h = g[3];
        float th = g[4] * (PI_F / 180.0f);
        float sn, cs;
        sincosf(th, &sn, &cs);   // precise: only 64 calls
        const float lx[4] = {-0.5f, 0.5f, 0.5f, -0.5f};
        const float ly[4] = {-0.5f, -0.5f, 0.5f, 0.5f};
#pragma unroll
        for (int k = 0; k < 4; k++) {
            float dx = w * lx[k], dy = h * ly[k];
            sgx[tid][k] = cx + dx * cs - dy * sn;
            sgy[tid][k] = cy + dx * sn + dy * cs;
        }
        sgar[tid] = w * h;
        float s = fmaxf(w, h) * 0.5f;
        sqx1[tid] = cx - s; sqy1[tid] = cy - s;
        sqx2[tid] = cx + s; sqy2[tid] = cy + s;
        sqar[tid] = (2.0f * s) * (2.0f * s);
        scol[tid] = 0;
    }
    __syncthreads();

    // -------- Phase 1: filter (half-row per thread) + dense base-sum iteration 0 ------
    if (gtid < NB * NA * 2) {
        int half = gtid & 1;
        int a = (gtid >> 1) & (NA - 1);
        int img = gtid >> 15;
        int aidx = img * NA + a;
        const float* p = anc + (size_t)aidx * 5;
        const float* q = ranc + (size_t)aidx * 5;
        float s0 = fmaxf(p[2], p[3]) * 0.5f;
        float ax1 = p[0] - s0, ay1 = p[1] - s0, ax2 = p[0] + s0, ay2 = p[1] + s0;
        float aar = (ax2 - ax1) * (ay2 - ay1);
        float s1 = fmaxf(q[2], q[3]) * 0.5f;
        float rx1 = q[0] - s1, ry1 = q[1] - s1, rx2 = q[0] + s1, ry2 = q[1] + s1;
        float rar = (rx2 - rx1) * (ry2 - ry1);
        int jb = (img << 5) + half * 16;

        int m = 0;   // number of gated (a,j) — each emits TWO entries
        unsigned fbits0 = 0, fbits1 = 0;
#pragma unroll
        for (int jj = 0; jj < 16; jj++) {
            float gx1 = sqx1[jb + jj], gy1 = sqy1[jb + jj];
            float gx2 = sqx2[jb + jj], gy2 = sqy2[jb + jj], gar = sqar[jb + jj];
            float wx = fmaxf(fminf(ax2, gx2) - fmaxf(ax1, gx1), 0.0f);
            float wy = fmaxf(fminf(ay2, gy2) - fmaxf(ay1, gy1), 0.0f);
            float i0 = wx * wy;
            bool f0 = gate(i0, aar + gar - i0 + 1e-8f);
            wx = fmaxf(fminf(rx2, gx2) - fmaxf(rx1, gx1), 0.0f);
            wy = fmaxf(fminf(ry2, gy2) - fmaxf(ry1, gy1), 0.0f);
            float i1 = wx * wy;
            bool f1 = gate(i1, rar + gar - i1 + 1e-8f);
            fbits0 |= ((unsigned)f0) << jj;
            fbits1 |= ((unsigned)f1) << jj;
            m += (int)(f0 | f1);
        }
        int incl = m;
#pragma unroll
        for (int off = 1; off < 32; off <<= 1) {
            int nn = __shfl_up_sync(0xffffffffu, incl, off);
            if (lane >= off) incl += nn;
        }
        int total = __shfl_sync(0xffffffffu, incl, 31);
        int base = 0;
        if (lane == 0 && total > 0) base = atomicAdd(&g_pairCount, 2 * total);
        base = __shfl_sync(0xffffffffu, base, 0);
        int off0 = base + 2 * (incl - m);
        unsigned both = fbits0 | fbits1;
        while (both) {
            int jj = __ffs(both) - 1;
            both &= both - 1;
            int j = half * 16 + jj;
            int f0 = (fbits0 >> jj) & 1, f1 = (fbits1 >> jj) & 1;
            int common = (img << 21) | (a << 7) | (j << 2);
            g_pairs[off0++] = common | (0 << 1) | f0;   // phase 0, do-clip = f0
            g_pairs[off0++] = common | (1 << 1) | f1;   // phase 1, do-clip = f1
        }
    }
    // dense base-sum, iteration 0
    {
        int i = gtid;
        if (i < 2 * HALF) {
            float4 v = c4[i];
            float s = baseterm(v.x) + baseterm(v.y) + baseterm(v.z) + baseterm(v.w);
            if (i < HALF) cs0 += s; else cs1 += s;
        }
    }

    grid_barrier(0);

    // -------- Phase 2: heavy clip over BALANCED per-block chunks (even-sized) --------
    {
        int total = g_pairCount;
        int chunk = ((total + 2 * NBLK - 1) / (2 * NBLK)) * 2;   // even per-block chunk
        int start = blockIdx.x * chunk;
        int end = start + chunk;
        if (end > total) end = total;
        const float lx[4] = {-0.5f, 0.5f, 0.5f, -0.5f};
        const float ly[4] = {-0.5f, -0.5f, 0.5f, 0.5f};
        for (int base = start; base < end; base += NTHR) {   // block-uniform loop
            int idx = base + tid;
            bool active = (idx < end);
            float iou = 0.0f;
            int code = 0;
            if (active) {
                code = g_pairs[idx];
                int doClip = code & 1;
                int ph = (code >> 1) & 1;
                int j = (code >> 2) & 31;
                int a = (code >> 7) & (NA - 1);
                int img = (code >> 21) & 1;
                if (doClip) {
                    const float* pp = (ph ? ranc : anc) + (size_t)(img * NA + a) * 5;
                    float cx = pp[0], cy = pp[1], w = pp[2], h = pp[3];
                    float th = pp[4] * (PI_F / 180.0f);
                    float sn, cs;
                    __sincosf(th, &sn, &cs);
                    int gj = (img << 5) + j;
                    float AX[4], AY[4], BX[4], BY[4];
#pragma unroll
                    for (int k = 0; k < 4; k++) {
                        float dx = w * lx[k], dy = h * ly[k];
                        AX[k] = dx * cs - dy * sn;
                        AY[k] = dx * sn + dy * cs;
                        BX[k] = sgx[gj][k] - cx;
                        BY[k] = sgy[gj][k] - cy;
                    }
                    float inter = quad_inter_area_f(AX, AY, BX, BY);
                    iou = __fdividef(inter, w * h + sgar[gj] - inter + 1e-8f);
                }
            }
            // combine: even lane holds phase0 (bf), odd lane phase1 (af)
            float other = __shfl_xor_sync(0xffffffffu, iou, 1);
            if (active && ((idx & 1) == 0)) {
                float bf = iou, af = other;
                int j = (code >> 2) & 31;
                int a = (code >> 7) & (NA - 1);
                int img = (code >> 21) & 1;
                int gj = (img << 5) + j;
                float md = fabsf(bf + 0.5f * af - fabsf(af - bf));
                g_md[img][a][j] = md;
                atomicMax(&g_rowkey[img][a], spack(md, (unsigned)j));
                if (md > 0.0f) atomicMax(&scol[gj], spack(md, (unsigned)a));
            }
        }
        // dense base-sum, iteration 1 (overlaps clip stalls)
        {
            int i = gtid + GSZ;
            if (i < 2 * HALF) {
                float4 v = c4[i];
                float s = baseterm(v.x) + baseterm(v.y) + baseterm(v.z) + baseterm(v.w);
                if (i < HALF) cs0 += s; else cs1 += s;
            }
        }
        __syncthreads();
        if (tid < NB * NM && scol[tid] > 0)
            atomicMax(&g_colkeyF[tid >> 5][tid & 31], scol[tid]);
    }

    grid_barrier(1);

    // ------- Phase 3: colmax + force + POS compaction + inline ignore-band corrections -
    __shared__ int sforce[NB * NM];
    __shared__ ll scolp[NB * NM];
    __shared__ int snp[NB];
    if (tid < NB * NM) {
        float v; unsigned ix;
        sdec(g_colkeyF[tid >> 5][tid & 31], v, ix);
        sforce[tid] = (v < 0.5f) ? (int)ix : -1;
        scolp[tid] = NEGK;
    }
    if (tid == 128) { snp[0] = 0; snp[1] = 0; }
    if (gtid == GSZ - 1) g_pairCount = 0;  // consumed; reset for next replay
    __syncthreads();

    if (gtid < NB * NA) {
        int a = gtid & (NA - 1);
        int img = gtid >> 14;
        int jb = img << 5;
        ll rk = g_rowkey[img][a];
        if (rk != 0) g_rowkey[img][a] = 0;  // restore identity
        float iomax; unsigned jm;
        sdec(rk, iomax, jm);
        bool pos = (iomax >= 0.5f);
#pragma unroll
        for (int j = 0; j < NM; j++) pos |= (sforce[jb + j] == a);
        if (pos) {
            const float4* mrow = (const float4*)g_md[img][a];
#pragma unroll
            for (int c = 0; c < 8; c++) {
                float4 m = mrow[c];
                atomicMax(&scolp[jb + c * 4 + 0], spack(m.x, (unsigned)a));
                atomicMax(&scolp[jb + c * 4 + 1], spack(m.y, (unsigned)a));
                atomicMax(&scolp[jb + c * 4 + 2], spack(m.z, (unsigned)a));
                atomicMax(&scolp[jb + c * 4 + 3], spack(m.w, (unsigned)a));
            }
        } else if (iomax >= 0.4f) {
            // ignore band: tgt=-1 -> subtract base contribution (inline, overlapped)
            const float* crow = cls + ((size_t)img * NA + a) * NC;
            float s = 0.0f;
#pragma unroll
            for (int c = 0; c < NC; c++) s += baseterm(crow[c]);
            if (img == 0) cs0 -= s; else cs1 -= s;
        }
        unsigned mask = __ballot_sync(0xffffffffu, pos);
        if (mask) {
            int leader = __ffs(mask) - 1;
            int rank = __popc(mask & ((1u << lane) - 1));
            int base = 0;
            if (lane == leader) base = atomicAdd(&g_listCount, __popc(mask));
            base = __shfl_sync(0xffffffffu, base, leader);
            if (pos)
                g_list[base + rank] = a | (img << 14) | ((int)jm << 16);
        }
        if (lane == 0 && mask) atomicAdd(&snp[img], __popc(mask));
    }
    __syncthreads();
    if (tid < NB * NM && scolp[tid] != NEGK)
        atomicMax(&g_colkeyP[tid >> 5][tid & 31], scolp[tid]);
    if (tid == 128 && snp[0]) atomicAdd(&g_numpos[0], snp[0]);
    if (tid == 129 && snp[1]) atomicAdd(&g_numpos[1], snp[1]);

    grid_barrier(2);

    // ---- stage final colkeyP into shared (decoded) ----
    __shared__ float smaxP[NB * NM];
    __shared__ int sargP[NB * NM];
    if (tid < NB * NM) {
        float v; unsigned ix;
        sdec(g_colkeyP[tid >> 5][tid & 31], v, ix);
        smaxP[tid] = v; sargP[tid] = (int)ix;
    }
    __syncthreads();

    // ---------------- Phase 4: POS corrections only ----------------
    {
        int nitems = g_listCount;
        for (int i = gtid; i < nitems; i += GSZ) {
            int code = g_list[i];
            int a = code & (NA - 1);
            int img = (code >> 14) & 1;
            int jm = (code >> 16) & 31;
            int jb = img << 5;
            const float* crow = cls + ((size_t)img * NA + a) * NC;
            float cc, rr = 0.0f;
            float mw = -1e30f;
            const float4* mrow = (const float4*)g_md[img][a];
#pragma unroll
            for (int c = 0; c < 8; c++) {
                float4 m = mrow[c];
                float mv[4] = {m.x, m.y, m.z, m.w};
#pragma unroll
                for (int k = 0; k < 4; k++) {
                    int j = c * 4 + k;
                    float md = mv[k];
                    bool pm = (md >= 0.5f) || (sargP[jb + j] == a);
                    float comp = pm ? (1.0f - smaxP[jb + j]) : md;
                    mw = fmaxf(mw, comp + md);
                }
            }
            const float* gt = ann + (size_t)(img * NM + jm) * 6;
            int lab = (int)gt[5];
            float xl = fminf(fmaxf(crow[lab], 0.0001f), 1.0f - 0.0001f);
            float posterm = 0.25f * (1.0f - xl) * (1.0f - xl) * (-__logf(xl + 1e-6f)) * (mw + 1.0f);
            cc = posterm - baseterm(crow[lab]);
            const float* ap = anc + (size_t)(img * NA + a) * 5;
            const float* rg = reg + (size_t)(img * NA + a) * 5;
            float tv[5];
            tv[0] = (gt[0] - ap[0]) / ap[2];
            tv[1] = (gt[1] - ap[1]) / ap[3];
            tv[2] = __logf(fmaxf(gt[2], 1.0f) / ap[2]);
            tv[3] = __logf(fmaxf(gt[3], 1.0f) / ap[3]);
            tv[4] = __tanf(gt[4] * (PI_F / 180.0f)) - __tanf(ap[4] * (PI_F / 180.0f));
            const float BETA = (float)(1.0 / 9.0);
#pragma unroll
            for (int k = 0; k < 5; k++) {
                float diff = fabsf(rg[k] - tv[k]);
                float sl = (diff < BETA) ? (0.5f * diff * diff / BETA) : (diff - 0.5f * BETA);
                rr += sl * mw;
            }
            if (img == 0) { cs0 += cc; rs0 += rr; } else { cs1 += cc; rs1 += rr; }
        }
    }

    // ---------------- block reduction + ticket finalize ----------------
    cs0 = warp_sum_f(cs0); cs1 = warp_sum_f(cs1);
    rs0 = warp_sum_f(rs0); rs1 = warp_sum_f(rs1);
    __shared__ float sc0[16], sc1[16], sr0[16], sr1[16];
    int warp = tid >> 5;
    if (lane == 0) { sc0[warp] = cs0; sc1[warp] = cs1; sr0[warp] = rs0; sr1[warp] = rs1; }
    __syncthreads();
    __shared__ bool lastf;
    if (tid == 0) {
        double c0 = 0.0, c1 = 0.0, r0 = 0.0, r1 = 0.0;
#pragma unroll
        for (int k = 0; k < 16; k++) {
            c0 += (double)sc0[k]; c1 += (double)sc1[k];
            r0 += (double)sr0[k]; r1 += (double)sr1[k];
        }
        if (c0 != 0.0) atomicAdd(&g_cls_sum[0], c0);
        if (c1 != 0.0) atomicAdd(&g_cls_sum[1], c1);
        if (r0 != 0.0) atomicAdd(&g_reg_sum[0], r0);
        if (r1 != 0.0) atomicAdd(&g_reg_sum[1], r1);
        __threadfence();
        unsigned tk = atomicAdd(&g_ticket, 1u);
        lastf = (tk == (unsigned)(NBLK - 1));
    }
    __syncthreads();
    if (lastf) {
        if (tid < NB * NM) {
            g_colkeyF[tid >> 5][tid & 31] = 0;
            g_colkeyP[tid >> 5][tid & 31] = NEGK;
        }
        if (tid == 64) g_listCount = 0;
        if (tid == 65) g_ticket = 0;
        if (tid == 66) { g_barCnt[0] = 0; g_barCnt[1] = 0; g_barCnt[2] = 0; }
        if (tid == 0) {
            double lc = 0.0, lr = 0.0;
#pragma unroll
            for (int i2 = 0; i2 < NB; i2++) {
                int np = g_numpos[i2];
                lc += g_cls_sum[i2] / fmax((double)np, 1.0);
                if (np > 0) lr += g_reg_sum[i2] / (double)(np * 5);
                g_cls_sum[i2] = 0.0; g_reg_sum[i2] = 0.0; g_numpos[i2] = 0;
            }
            out[0] = (float)(lc / (double)NB);
            out[1] = (float)(lr / (double)NB);
        }
    }
}

// ---------------- launcher: ONE kernel ----------------
extern "C" void kernel_launch(void* const* d_in, const int* in_sizes, int n_in,
                              void* d_out, int out_size) {
    const float* cls  = (const float*)d_in[0];
    const float* reg  = (const float*)d_in[1];
    const float* anc  = (const float*)d_in[2];
    const float* ranc = (const float*)d_in[3];
    const float* ann  = (const float*)d_in[4];
    float* out = (float*)d_out;

    k_all<<<NBLK, NTHR>>>(cls, reg, anc, ranc, ann, out);
}